// round 2
// baseline (speedup 1.0000x reference)
#include <cuda_runtime.h>
#include <cuda_bf16.h>
#include <cstdint>
#include <cstddef>

// Problem constants
#define BATCH   512
#define NATOMS  32
#define DIM     512
#define NROWS   (BATCH * NATOMS)     // 16384
#define LHID    6
#define LOUT    6

// ---------------------------------------------------------------------------
// Scratch (static device globals; allocation-free per harness rules)
// ---------------------------------------------------------------------------
__device__ float g_V[(size_t)NROWS * DIM];    // 32 MB
__device__ float g_H[(size_t)NROWS * DIM];    // 32 MB
__device__ float g_mol[(size_t)BATCH * DIM];  // 1 MB
__device__ float g_mol2[(size_t)BATCH * DIM]; // 1 MB

// ---------------------------------------------------------------------------
// 1) Gather: V[row,:] = embed[fp[row],:]
// ---------------------------------------------------------------------------
__global__ void gather_embed(const int* __restrict__ fp,
                             const float* __restrict__ embed) {
    int row = blockIdx.x;                  // 16384 blocks, 128 threads
    int f = fp[row];
    const float4* src = (const float4*)(embed + (size_t)f * DIM);
    float4* dst = (float4*)(g_V + (size_t)row * DIM);
    dst[threadIdx.x] = src[threadIdx.x];   // 128 * 16B = 2 KB row
}

// ---------------------------------------------------------------------------
// 2) Tiled SGEMM: C[M,N] = act(A[M,K] @ B[K,N] + bias[N])
//    128x128x16 tile, 8x8 microtile, 256 threads.
// ---------------------------------------------------------------------------
template<int BM, int BN, int BK, int TM, int TN, bool RELU>
__global__ void sgemm_bias_kernel(const float* __restrict__ A,
                                  const float* __restrict__ B,
                                  const float* __restrict__ bias,
                                  float* __restrict__ C,
                                  int M, int N, int K) {
    constexpr int NT = (BM / TM) * (BN / TN);
    __shared__ float As[BK][BM + 4];
    __shared__ float Bs[BK][BN + 4];

    const int tid = threadIdx.x;
    constexpr int TCOLS = BN / TN;
    const int tx = tid % TCOLS;
    const int ty = tid / TCOLS;
    const int m0 = blockIdx.y * BM;
    const int n0 = blockIdx.x * BN;

    float acc[TM][TN];
#pragma unroll
    for (int i = 0; i < TM; i++)
#pragma unroll
        for (int j = 0; j < TN; j++) acc[i][j] = 0.0f;

    for (int k0 = 0; k0 < K; k0 += BK) {
        // Load A tile (BM x BK), store transposed into As[k][m]
        for (int i = tid; i < BM * BK / 4; i += NT) {
            int r = i / (BK / 4);
            int c = (i % (BK / 4)) * 4;
            float4 v = *(const float4*)(A + (size_t)(m0 + r) * K + k0 + c);
            As[c + 0][r] = v.x;
            As[c + 1][r] = v.y;
            As[c + 2][r] = v.z;
            As[c + 3][r] = v.w;
        }
        // Load B tile (BK x BN)
        for (int i = tid; i < BK * BN / 4; i += NT) {
            int r = i / (BN / 4);
            int c = (i % (BN / 4)) * 4;
            *(float4*)&Bs[r][c] = *(const float4*)(B + (size_t)(k0 + r) * N + n0 + c);
        }
        __syncthreads();
#pragma unroll
        for (int k = 0; k < BK; k++) {
            float a[TM], bb[TN];
#pragma unroll
            for (int i = 0; i < TM; i += 4)
                *(float4*)&a[i] = *(const float4*)&As[k][ty * TM + i];
#pragma unroll
            for (int j = 0; j < TN; j += 4)
                *(float4*)&bb[j] = *(const float4*)&Bs[k][tx * TN + j];
#pragma unroll
            for (int i = 0; i < TM; i++)
#pragma unroll
                for (int j = 0; j < TN; j++)
                    acc[i][j] = fmaf(a[i], bb[j], acc[i][j]);
        }
        __syncthreads();
    }

#pragma unroll
    for (int i = 0; i < TM; i++) {
        int m = m0 + ty * TM + i;
#pragma unroll
        for (int j = 0; j < TN; j++) {
            int n = n0 + tx * TN + j;
            float v = acc[i][j] + bias[n];
            if (RELU) v = fmaxf(v, 0.0f);
            C[(size_t)m * N + n] = v;
        }
    }
}

// ---------------------------------------------------------------------------
// 3) Per-molecule message passing + L2 row normalize:
//    h = H[b]  (32 x 512 in smem)
//    out = h + A_b @ h ; V[b] = out / max(||out||_row, 1e-12)
// ---------------------------------------------------------------------------
#define MSG_SMEM_BYTES ((NATOMS * DIM + NATOMS * NATOMS + NATOMS) * (int)sizeof(float))

__global__ void msg_norm_kernel(const float* __restrict__ adj) {
    extern __shared__ float sm[];
    float* h    = sm;                       // [32][512]
    float* Asub = sm + NATOMS * DIM;        // [32][32]
    float* invn = Asub + NATOMS * NATOMS;   // [32]

    const int b   = blockIdx.x;
    const int tid = threadIdx.x;            // 256 threads

    // adjacency block
    for (int i = tid; i < NATOMS * NATOMS; i += 256)
        Asub[i] = adj[(size_t)b * NATOMS * NATOMS + i];

    // H block (64 KB) via float4
    {
        const float4* src = (const float4*)(g_H + (size_t)b * NATOMS * DIM);
        float4* dst = (float4*)h;
#pragma unroll
        for (int i = 0; i < (NATOMS * DIM / 4) / 256; i++)
            dst[tid + i * 256] = src[tid + i * 256];
    }
    __syncthreads();

    // Each thread: 16 atoms x 4 dims
    const int d  = tid & 127;               // 0..127
    const int n0 = (tid >> 7) * 16;         // 0 or 16
    float out[16][4];
#pragma unroll
    for (int n = 0; n < 16; n++)
#pragma unroll
        for (int j = 0; j < 4; j++)
            out[n][j] = h[(n0 + n) * DIM + d + j * 128];

    for (int m = 0; m < NATOMS; m++) {
        float hm0 = h[m * DIM + d];
        float hm1 = h[m * DIM + d + 128];
        float hm2 = h[m * DIM + d + 256];
        float hm3 = h[m * DIM + d + 384];
#pragma unroll
        for (int n = 0; n < 16; n++) {
            float a = Asub[(n0 + n) * NATOMS + m];   // warp-uniform broadcast
            out[n][0] = fmaf(a, hm0, out[n][0]);
            out[n][1] = fmaf(a, hm1, out[n][1]);
            out[n][2] = fmaf(a, hm2, out[n][2]);
            out[n][3] = fmaf(a, hm3, out[n][3]);
        }
    }
    __syncthreads();   // all reads of h complete before in-place overwrite

#pragma unroll
    for (int n = 0; n < 16; n++)
#pragma unroll
        for (int j = 0; j < 4; j++)
            h[(n0 + n) * DIM + d + j * 128] = out[n][j];
    __syncthreads();

    // Row norms: warp w reduces rows 4w..4w+3
    {
        const int w = tid >> 5, lane = tid & 31;
        for (int r = w * 4; r < w * 4 + 4; r++) {
            float ss = 0.0f;
#pragma unroll
            for (int i = 0; i < DIM / 32; i++) {
                float x = h[r * DIM + lane + i * 32];
                ss = fmaf(x, x, ss);
            }
#pragma unroll
            for (int o = 16; o; o >>= 1) ss += __shfl_xor_sync(0xFFFFFFFFu, ss, o);
            if (lane == 0) invn[r] = 1.0f / fmaxf(sqrtf(ss), 1e-12f);
        }
    }
    __syncthreads();

    // Scaled write -> V
    float* dst = g_V + (size_t)b * NATOMS * DIM;
#pragma unroll
    for (int i = 0; i < (NATOMS * DIM) / 256; i++) {
        int idx = tid + i * 256;
        dst[idx] = h[idx] * invn[idx >> 9];
    }
}

// ---------------------------------------------------------------------------
// 4) Mean pool over atoms: mol[b,d] = mean_n V[b,n,d]
// ---------------------------------------------------------------------------
__global__ void pool_kernel() {
    int b = blockIdx.x;
    for (int d = threadIdx.x; d < DIM; d += 256) {
        float s = 0.0f;
        for (int n = 0; n < NATOMS; n++)
            s += g_V[((size_t)b * NATOMS + n) * DIM + d];
        g_mol[(size_t)b * DIM + d] = s * (1.0f / NATOMS);
    }
}

// ---------------------------------------------------------------------------
// 5) Final projection: out[b] = mol[b,:] . Wp + bp
// ---------------------------------------------------------------------------
__global__ void final_kernel(const float* __restrict__ mol,
                             const float* __restrict__ Wp,
                             const float* __restrict__ bp,
                             float* __restrict__ out) {
    int b = blockIdx.x;                    // 512 blocks, 128 threads
    float s = 0.0f;
    for (int d = threadIdx.x; d < DIM; d += 128)
        s = fmaf(mol[(size_t)b * DIM + d], Wp[d], s);
    __shared__ float red[4];
#pragma unroll
    for (int o = 16; o; o >>= 1) s += __shfl_down_sync(0xFFFFFFFFu, s, o);
    if ((threadIdx.x & 31) == 0) red[threadIdx.x >> 5] = s;
    __syncthreads();
    if (threadIdx.x == 0)
        out[b] = red[0] + red[1] + red[2] + red[3] + bp[0];
}

// ---------------------------------------------------------------------------
// Launcher
// ---------------------------------------------------------------------------
extern "C" void kernel_launch(void* const* d_in, const int* in_sizes, int n_in,
                              void* d_out, int out_size) {
    const int*   fp    = (const int*)  d_in[0];
    const float* adj   = (const float*)d_in[1];
    const float* embed = (const float*)d_in[2];
    const float* Wf    = (const float*)d_in[3];
    const float* bf    = (const float*)d_in[4];
    const float* Wo    = (const float*)d_in[5];
    const float* bo    = (const float*)d_in[6];
    const float* Wp    = (const float*)d_in[7];
    const float* bp    = (const float*)d_in[8];
    float* out = (float*)d_out;

    float *V, *H, *M0, *M1;
    cudaGetSymbolAddress((void**)&V,  g_V);
    cudaGetSymbolAddress((void**)&H,  g_H);
    cudaGetSymbolAddress((void**)&M0, g_mol);
    cudaGetSymbolAddress((void**)&M1, g_mol2);

    cudaFuncSetAttribute(msg_norm_kernel,
                         cudaFuncAttributeMaxDynamicSharedMemorySize,
                         MSG_SMEM_BYTES);

    gather_embed<<<NROWS, 128>>>(fp, embed);

    for (int l = 0; l < LHID; l++) {
        sgemm_bias_kernel<128, 128, 16, 8, 8, true>
            <<<dim3(DIM / 128, NROWS / 128), 256>>>(
                V, Wf + (size_t)l * DIM * DIM, bf + (size_t)l * DIM, H,
                NROWS, DIM, DIM);
        msg_norm_kernel<<<BATCH, 256, MSG_SMEM_BYTES>>>(adj);
    }

    pool_kernel<<<BATCH, 256>>>();

    const float* src = M0;
    float* dst = M1;
    for (int i = 0; i < LOUT; i++) {
        sgemm_bias_kernel<32, 64, 16, 2, 4, true>
            <<<dim3(DIM / 64, BATCH / 32), 256>>>(
                src, Wo + (size_t)i * DIM * DIM, bo + (size_t)i * DIM,
                dst, BATCH, DIM, DIM);
        const float* t = src; src = dst; dst = (float*)t;
    }
    // after even number of swaps, result is back in M0 (== src)

    final_kernel<<<BATCH, 128>>>(src, Wp, bp, out);
}

// round 4
// speedup vs baseline: 1.9930x; 1.9930x over previous
#include <cuda_runtime.h>
#include <cuda_fp16.h>
#include <cstdint>
#include <cstddef>

// Problem constants
#define BATCH   512
#define NATOMS  32
#define DIM     512
#define NROWS   (BATCH * NATOMS)     // 16384
#define LHID    6
#define LOUT    6

// ---------------------------------------------------------------------------
// Scratch (static device globals; allocation-free per harness rules)
// ---------------------------------------------------------------------------
__device__ float  g_V [(size_t)NROWS * DIM];        // 32 MB fp32 (for pool)
__device__ float  g_H [(size_t)NROWS * DIM];        // 32 MB fp32 GEMM out
__device__ __half g_Vh[(size_t)NROWS * DIM];        // 16 MB activation hi
__device__ __half g_Vl[(size_t)NROWS * DIM];        // 16 MB activation lo
__device__ __half g_Wth[(size_t)LHID * DIM * DIM];  // 3 MB weight hi (K-major)
__device__ __half g_Wtl[(size_t)LHID * DIM * DIM];  // 3 MB weight lo (K-major)
__device__ float  g_mol [(size_t)BATCH * DIM];
__device__ float  g_mol2[(size_t)BATCH * DIM];

// ---------------------------------------------------------------------------
// 0) Weight transpose + fp16 hi/lo split: Wt*[l][n][k] = split(Wf[l][k][n])
// ---------------------------------------------------------------------------
__global__ void transpose_split_w(const float* __restrict__ Wf) {
    __shared__ float t[32][33];
    const int l  = blockIdx.z;
    const int k0 = blockIdx.y * 32, n0 = blockIdx.x * 32;
    const int tx = threadIdx.x, ty = threadIdx.y;     // 32 x 8
    const float* src = Wf + (size_t)l * DIM * DIM;
#pragma unroll
    for (int i = 0; i < 4; i++)
        t[ty + i * 8][tx] = src[(size_t)(k0 + ty + i * 8) * DIM + n0 + tx];
    __syncthreads();
#pragma unroll
    for (int i = 0; i < 4; i++) {
        float v = t[tx][ty + i * 8];                  // = Wf[k0+tx][n0+ty+i*8]
        size_t dst = (size_t)l * DIM * DIM + (size_t)(n0 + ty + i * 8) * DIM + k0 + tx;
        __half hi = __float2half_rn(v);
        g_Wth[dst] = hi;
        g_Wtl[dst] = __float2half_rn(v - __half2float(hi));
    }
}

// ---------------------------------------------------------------------------
// 1) Gather + split: Vh/Vl[row,:] = split(embed[fp[row],:])
// ---------------------------------------------------------------------------
__global__ void gather_embed(const int* __restrict__ fp,
                             const float* __restrict__ embed) {
    int row = blockIdx.x;                  // 16384 blocks, 128 threads
    int f = fp[row];
    float4 v = ((const float4*)(embed + (size_t)f * DIM))[threadIdx.x];
    size_t o = (size_t)row * DIM + threadIdx.x * 4;
    __half hx = __float2half_rn(v.x), hy = __float2half_rn(v.y);
    __half hz = __float2half_rn(v.z), hw = __float2half_rn(v.w);
    *(__half2*)(g_Vh + o)     = __halves2half2(hx, hy);
    *(__half2*)(g_Vh + o + 2) = __halves2half2(hz, hw);
    *(__half2*)(g_Vl + o)     = __halves2half2(__float2half_rn(v.x - __half2float(hx)),
                                               __float2half_rn(v.y - __half2float(hy)));
    *(__half2*)(g_Vl + o + 2) = __halves2half2(__float2half_rn(v.z - __half2float(hz)),
                                               __float2half_rn(v.w - __half2float(hw)));
}

// ---------------------------------------------------------------------------
// 2) fp16-split tensor-core GEMM: H = relu(V @ Wf + bf)
//    A = Vh/Vl [NROWS][DIM] row-major, B = Wth/Wtl [DIM(n)][DIM(k)] K-major.
//    CTA 128x128, 8 warps of 64x32, K-chunk 32, mma.m16n8k16.
// ---------------------------------------------------------------------------
#define KC   32
#define APAD 40   // smem row stride in halves (conflict-free for frag loads)

__device__ __forceinline__ void mma16816(float* d, const uint32_t* a, const uint32_t* b) {
    asm volatile(
        "mma.sync.aligned.m16n8k16.row.col.f32.f16.f16.f32 "
        "{%0,%1,%2,%3}, {%4,%5,%6,%7}, {%8,%9}, {%0,%1,%2,%3};"
        : "+f"(d[0]), "+f"(d[1]), "+f"(d[2]), "+f"(d[3])
        : "r"(a[0]), "r"(a[1]), "r"(a[2]), "r"(a[3]), "r"(b[0]), "r"(b[1]));
}

__global__ void __launch_bounds__(256, 2)
hgemm_split(const __half* __restrict__ Ah, const __half* __restrict__ Al,
            const __half* __restrict__ Bh, const __half* __restrict__ Bl,
            const float* __restrict__ bias, float* __restrict__ C) {
    __shared__ __half sAh[128 * APAD], sAl[128 * APAD];
    __shared__ __half sBh[128 * APAD], sBl[128 * APAD];

    const int tid = threadIdx.x;
    const int lane = tid & 31, wid = tid >> 5;
    const int m0 = blockIdx.y * 128, n0 = blockIdx.x * 128;
    const int wm = (wid >> 2) * 64, wn = (wid & 3) * 32;
    const int g = lane >> 2, tg = lane & 3;           // groupID, thread-in-group

    float acc[4][4][4];
#pragma unroll
    for (int i = 0; i < 4; i++)
#pragma unroll
        for (int j = 0; j < 4; j++)
#pragma unroll
            for (int r = 0; r < 4; r++) acc[i][j][r] = 0.0f;

    for (int c = 0; c < DIM / KC; c++) {
        const int k0 = c * KC;
        // --- stage 128x32 halves of each of the 4 operands ---
#pragma unroll
        for (int i = 0; i < 2; i++) {
            int s = tid + i * 256;                    // 0..511
            int r = s >> 2, q = s & 3;                // row, uint4 index
            int so = r * APAD + q * 8;
            *(uint4*)&sAh[so] = *(const uint4*)(Ah + (size_t)(m0 + r) * DIM + k0 + q * 8);
            *(uint4*)&sAl[so] = *(const uint4*)(Al + (size_t)(m0 + r) * DIM + k0 + q * 8);
            *(uint4*)&sBh[so] = *(const uint4*)(Bh + (size_t)(n0 + r) * DIM + k0 + q * 8);
            *(uint4*)&sBl[so] = *(const uint4*)(Bl + (size_t)(n0 + r) * DIM + k0 + q * 8);
        }
        __syncthreads();

#pragma unroll
        for (int ks = 0; ks < KC / 16; ks++) {
            const int kk = ks * 16;
            uint32_t a_hi[4][4], a_lo[4][4], b[4][2];
            // A hi frags
#pragma unroll
            for (int mf = 0; mf < 4; mf++) {
                int row = wm + mf * 16 + g;
                a_hi[mf][0] = *(const uint32_t*)&sAh[row * APAD + kk + tg * 2];
                a_hi[mf][1] = *(const uint32_t*)&sAh[(row + 8) * APAD + kk + tg * 2];
                a_hi[mf][2] = *(const uint32_t*)&sAh[row * APAD + kk + 8 + tg * 2];
                a_hi[mf][3] = *(const uint32_t*)&sAh[(row + 8) * APAD + kk + 8 + tg * 2];
            }
            // B hi frags ; term1 = Ah*Bh
#pragma unroll
            for (int nf = 0; nf < 4; nf++) {
                int rn = wn + nf * 8 + g;
                b[nf][0] = *(const uint32_t*)&sBh[rn * APAD + kk + tg * 2];
                b[nf][1] = *(const uint32_t*)&sBh[rn * APAD + kk + 8 + tg * 2];
            }
#pragma unroll
            for (int mf = 0; mf < 4; mf++)
#pragma unroll
                for (int nf = 0; nf < 4; nf++)
                    mma16816(acc[mf][nf], a_hi[mf], b[nf]);
            // A lo frags ; term2 = Al*Bh
#pragma unroll
            for (int mf = 0; mf < 4; mf++) {
                int row = wm + mf * 16 + g;
                a_lo[mf][0] = *(const uint32_t*)&sAl[row * APAD + kk + tg * 2];
                a_lo[mf][1] = *(const uint32_t*)&sAl[(row + 8) * APAD + kk + tg * 2];
                a_lo[mf][2] = *(const uint32_t*)&sAl[row * APAD + kk + 8 + tg * 2];
                a_lo[mf][3] = *(const uint32_t*)&sAl[(row + 8) * APAD + kk + 8 + tg * 2];
            }
#pragma unroll
            for (int mf = 0; mf < 4; mf++)
#pragma unroll
                for (int nf = 0; nf < 4; nf++)
                    mma16816(acc[mf][nf], a_lo[mf], b[nf]);
            // B lo frags ; term3 = Ah*Bl
#pragma unroll
            for (int nf = 0; nf < 4; nf++) {
                int rn = wn + nf * 8 + g;
                b[nf][0] = *(const uint32_t*)&sBl[rn * APAD + kk + tg * 2];
                b[nf][1] = *(const uint32_t*)&sBl[rn * APAD + kk + 8 + tg * 2];
            }
#pragma unroll
            for (int mf = 0; mf < 4; mf++)
#pragma unroll
                for (int nf = 0; nf < 4; nf++)
                    mma16816(acc[mf][nf], a_hi[mf], b[nf]);
        }
        __syncthreads();
    }

    // Epilogue: bias + relu, fp32 out
#pragma unroll
    for (int mf = 0; mf < 4; mf++) {
        int r0 = m0 + wm + mf * 16 + g;
#pragma unroll
        for (int nf = 0; nf < 4; nf++) {
            int col = n0 + wn + nf * 8 + tg * 2;
            float b0 = bias[col], b1 = bias[col + 1];
            float2 o0, o1;
            o0.x = fmaxf(acc[mf][nf][0] + b0, 0.0f);
            o0.y = fmaxf(acc[mf][nf][1] + b1, 0.0f);
            o1.x = fmaxf(acc[mf][nf][2] + b0, 0.0f);
            o1.y = fmaxf(acc[mf][nf][3] + b1, 0.0f);
            *(float2*)(C + (size_t)r0 * DIM + col) = o0;
            *(float2*)(C + (size_t)(r0 + 8) * DIM + col) = o1;
        }
    }
}

// ---------------------------------------------------------------------------
// 3) Per-molecule message passing + L2 row normalize; writes fp32 V and
//    fp16 hi/lo split for the next GEMM.
// ---------------------------------------------------------------------------
#define MSG_SMEM_BYTES ((NATOMS * DIM + NATOMS * NATOMS + NATOMS) * (int)sizeof(float))

__global__ void msg_norm_kernel(const float* __restrict__ adj) {
    extern __shared__ float sm[];
    float* h    = sm;                       // [32][512]
    float* Asub = sm + NATOMS * DIM;        // [32][32]
    float* invn = Asub + NATOMS * NATOMS;   // [32]

    const int b   = blockIdx.x;
    const int tid = threadIdx.x;            // 256 threads

    for (int i = tid; i < NATOMS * NATOMS; i += 256)
        Asub[i] = adj[(size_t)b * NATOMS * NATOMS + i];
    {
        const float4* src = (const float4*)(g_H + (size_t)b * NATOMS * DIM);
        float4* dst = (float4*)h;
#pragma unroll
        for (int i = 0; i < (NATOMS * DIM / 4) / 256; i++)
            dst[tid + i * 256] = src[tid + i * 256];
    }
    __syncthreads();

    const int d  = tid & 127;
    const int n0 = (tid >> 7) * 16;
    float out[16][4];
#pragma unroll
    for (int n = 0; n < 16; n++)
#pragma unroll
        for (int j = 0; j < 4; j++)
            out[n][j] = h[(n0 + n) * DIM + d + j * 128];

    for (int m = 0; m < NATOMS; m++) {
        float hm0 = h[m * DIM + d];
        float hm1 = h[m * DIM + d + 128];
        float hm2 = h[m * DIM + d + 256];
        float hm3 = h[m * DIM + d + 384];
#pragma unroll
        for (int n = 0; n < 16; n++) {
            float a = Asub[(n0 + n) * NATOMS + m];
            out[n][0] = fmaf(a, hm0, out[n][0]);
            out[n][1] = fmaf(a, hm1, out[n][1]);
            out[n][2] = fmaf(a, hm2, out[n][2]);
            out[n][3] = fmaf(a, hm3, out[n][3]);
        }
    }
    __syncthreads();

#pragma unroll
    for (int n = 0; n < 16; n++)
#pragma unroll
        for (int j = 0; j < 4; j++)
            h[(n0 + n) * DIM + d + j * 128] = out[n][j];
    __syncthreads();

    {
        const int w = tid >> 5, lane = tid & 31;
        for (int r = w * 4; r < w * 4 + 4; r++) {
            float ss = 0.0f;
#pragma unroll
            for (int i = 0; i < DIM / 32; i++) {
                float x = h[r * DIM + lane + i * 32];
                ss = fmaf(x, x, ss);
            }
#pragma unroll
            for (int o = 16; o; o >>= 1) ss += __shfl_xor_sync(0xFFFFFFFFu, ss, o);
            if (lane == 0) invn[r] = 1.0f / fmaxf(sqrtf(ss), 1e-12f);
        }
    }
    __syncthreads();

    const size_t base = (size_t)b * NATOMS * DIM;
#pragma unroll
    for (int i = 0; i < (NATOMS * DIM) / 256; i++) {
        int idx = tid + i * 256;
        float v = h[idx] * invn[idx >> 9];
        g_V[base + idx] = v;
        __half hi = __float2half_rn(v);
        g_Vh[base + idx] = hi;
        g_Vl[base + idx] = __float2half_rn(v - __half2float(hi));
    }
}

// ---------------------------------------------------------------------------
// 4) Mean pool
// ---------------------------------------------------------------------------
__global__ void pool_kernel() {
    int b = blockIdx.x;
    for (int d = threadIdx.x; d < DIM; d += 256) {
        float s = 0.0f;
        for (int n = 0; n < NATOMS; n++)
            s += g_V[((size_t)b * NATOMS + n) * DIM + d];
        g_mol[(size_t)b * DIM + d] = s * (1.0f / NATOMS);
    }
}

// ---------------------------------------------------------------------------
// 5) Scalar SGEMM for the small MLP
// ---------------------------------------------------------------------------
template<int BM, int BN, int BK, int TM, int TN, bool RELU>
__global__ void sgemm_bias_kernel(const float* __restrict__ A,
                                  const float* __restrict__ B,
                                  const float* __restrict__ bias,
                                  float* __restrict__ C,
                                  int M, int N, int K) {
    constexpr int NT = (BM / TM) * (BN / TN);
    __shared__ float As[BK][BM + 4];
    __shared__ float Bs[BK][BN + 4];

    const int tid = threadIdx.x;
    constexpr int TCOLS = BN / TN;
    const int tx = tid % TCOLS;
    const int ty = tid / TCOLS;
    const int m0 = blockIdx.y * BM;
    const int n0 = blockIdx.x * BN;

    float acc[TM][TN];
#pragma unroll
    for (int i = 0; i < TM; i++)
#pragma unroll
        for (int j = 0; j < TN; j++) acc[i][j] = 0.0f;

    for (int k0 = 0; k0 < K; k0 += BK) {
        for (int i = tid; i < BM * BK / 4; i += NT) {
            int r = i / (BK / 4);
            int c = (i % (BK / 4)) * 4;
            float4 v = *(const float4*)(A + (size_t)(m0 + r) * K + k0 + c);
            As[c + 0][r] = v.x;
            As[c + 1][r] = v.y;
            As[c + 2][r] = v.z;
            As[c + 3][r] = v.w;
        }
        for (int i = tid; i < BK * BN / 4; i += NT) {
            int r = i / (BN / 4);
            int c = (i % (BN / 4)) * 4;
            *(float4*)&Bs[r][c] = *(const float4*)(B + (size_t)(k0 + r) * N + n0 + c);
        }
        __syncthreads();
#pragma unroll
        for (int k = 0; k < BK; k++) {
            float a[TM], bb[TN];
#pragma unroll
            for (int i = 0; i < TM; i++) a[i] = As[k][ty * TM + i];
#pragma unroll
            for (int j = 0; j < TN; j++) bb[j] = Bs[k][tx * TN + j];
#pragma unroll
            for (int i = 0; i < TM; i++)
#pragma unroll
                for (int j = 0; j < TN; j++)
                    acc[i][j] = fmaf(a[i], bb[j], acc[i][j]);
        }
        __syncthreads();
    }

#pragma unroll
    for (int i = 0; i < TM; i++) {
        int m = m0 + ty * TM + i;
#pragma unroll
        for (int j = 0; j < TN; j++) {
            int n = n0 + tx * TN + j;
            float v = acc[i][j] + bias[n];
            if (RELU) v = fmaxf(v, 0.0f);
            C[(size_t)m * N + n] = v;
        }
    }
}

// ---------------------------------------------------------------------------
// 6) Final projection
// ---------------------------------------------------------------------------
__global__ void final_kernel(const float* __restrict__ mol,
                             const float* __restrict__ Wp,
                             const float* __restrict__ bp,
                             float* __restrict__ out) {
    int b = blockIdx.x;
    float s = 0.0f;
    for (int d = threadIdx.x; d < DIM; d += 128)
        s = fmaf(mol[(size_t)b * DIM + d], Wp[d], s);
    __shared__ float red[4];
#pragma unroll
    for (int o = 16; o; o >>= 1) s += __shfl_down_sync(0xFFFFFFFFu, s, o);
    if ((threadIdx.x & 31) == 0) red[threadIdx.x >> 5] = s;
    __syncthreads();
    if (threadIdx.x == 0)
        out[b] = red[0] + red[1] + red[2] + red[3] + bp[0];
}

// ---------------------------------------------------------------------------
// Launcher
// ---------------------------------------------------------------------------
extern "C" void kernel_launch(void* const* d_in, const int* in_sizes, int n_in,
                              void* d_out, int out_size) {
    const int*   fp    = (const int*)  d_in[0];
    const float* adj   = (const float*)d_in[1];
    const float* embed = (const float*)d_in[2];
    const float* Wf    = (const float*)d_in[3];
    const float* bf    = (const float*)d_in[4];
    const float* Wo    = (const float*)d_in[5];
    const float* bo    = (const float*)d_in[6];
    const float* Wp    = (const float*)d_in[7];
    const float* bp    = (const float*)d_in[8];
    float* out = (float*)d_out;

    float *H, *M0, *M1;
    __half *Vh, *Vl, *Wth, *Wtl;
    cudaGetSymbolAddress((void**)&H,   g_H);
    cudaGetSymbolAddress((void**)&Vh,  g_Vh);
    cudaGetSymbolAddress((void**)&Vl,  g_Vl);
    cudaGetSymbolAddress((void**)&Wth, g_Wth);
    cudaGetSymbolAddress((void**)&Wtl, g_Wtl);
    cudaGetSymbolAddress((void**)&M0,  g_mol);
    cudaGetSymbolAddress((void**)&M1,  g_mol2);

    cudaFuncSetAttribute(msg_norm_kernel,
                         cudaFuncAttributeMaxDynamicSharedMemorySize, MSG_SMEM_BYTES);

    transpose_split_w<<<dim3(16, 16, LHID), dim3(32, 8)>>>(Wf);
    gather_embed<<<NROWS, 128>>>(fp, embed);

    for (int l = 0; l < LHID; l++) {
        hgemm_split<<<dim3(DIM / 128, NROWS / 128), 256>>>(
            Vh, Vl,
            Wth + (size_t)l * DIM * DIM, Wtl + (size_t)l * DIM * DIM,
            bf + (size_t)l * DIM, H);
        msg_norm_kernel<<<BATCH, 256, MSG_SMEM_BYTES>>>(adj);
    }

    pool_kernel<<<BATCH, 256>>>();

    const float* src = M0;
    float* dst = M1;
    for (int i = 0; i < LOUT; i++) {
        sgemm_bias_kernel<32, 64, 16, 2, 4, true>
            <<<dim3(DIM / 64, BATCH / 32), 256>>>(
                src, Wo + (size_t)i * DIM * DIM, bo + (size_t)i * DIM,
                dst, BATCH, DIM, DIM);
        const float* t = src; src = dst; dst = (float*)t;
    }

    final_kernel<<<BATCH, 128>>>(src, Wp, bp, out);
}

// round 5
// speedup vs baseline: 2.1889x; 1.0983x over previous
#include <cuda_runtime.h>
#include <cuda_fp16.h>
#include <cstdint>
#include <cstddef>

// Problem constants
#define BATCH   512
#define NATOMS  32
#define DIM     512
#define NROWS   (BATCH * NATOMS)     // 16384
#define LHID    6
#define LOUT    6

// ---------------------------------------------------------------------------
// Scratch (static device globals; allocation-free per harness rules)
// ---------------------------------------------------------------------------
__device__ float  g_H [(size_t)NROWS * DIM];                      // 32 MB GEMM out
__device__ __align__(16) __half g_Vh[(size_t)NROWS * DIM];        // 16 MB act hi
__device__ __align__(16) __half g_Vl[(size_t)NROWS * DIM];        // 16 MB act lo
__device__ __align__(16) __half g_Wth[(size_t)LHID * DIM * DIM];  // 3 MB W hi (K-major)
__device__ __align__(16) __half g_Wtl[(size_t)LHID * DIM * DIM];  // 3 MB W lo (K-major)
__device__ float  g_mol [(size_t)BATCH * DIM];
__device__ float  g_mol2[(size_t)BATCH * DIM];

// ---------------------------------------------------------------------------
// PTX helpers
// ---------------------------------------------------------------------------
__device__ __forceinline__ uint32_t smem_to_u32(const void* p) {
    uint32_t a;
    asm("{ .reg .u64 t; cvta.to.shared.u64 t, %1; cvt.u32.u64 %0, t; }" : "=r"(a) : "l"(p));
    return a;
}
#define CP_ASYNC16(dst, src) \
    asm volatile("cp.async.cg.shared.global [%0], [%1], 16;" :: "r"(dst), "l"(src))
#define CP_COMMIT() asm volatile("cp.async.commit_group;" ::: "memory")
#define CP_WAIT0()  asm volatile("cp.async.wait_group 0;" ::: "memory")
#define LDSM4(R0, R1, R2, R3, addr) \
    asm volatile("ldmatrix.sync.aligned.m8n8.x4.shared.b16 {%0,%1,%2,%3}, [%4];" \
        : "=r"(R0), "=r"(R1), "=r"(R2), "=r"(R3) : "r"(addr))

__device__ __forceinline__ void mma16816(float* d, const uint32_t* a, const uint32_t* b) {
    asm volatile(
        "mma.sync.aligned.m16n8k16.row.col.f32.f16.f16.f32 "
        "{%0,%1,%2,%3}, {%4,%5,%6,%7}, {%8,%9}, {%0,%1,%2,%3};"
        : "+f"(d[0]), "+f"(d[1]), "+f"(d[2]), "+f"(d[3])
        : "r"(a[0]), "r"(a[1]), "r"(a[2]), "r"(a[3]), "r"(b[0]), "r"(b[1]));
}

// ---------------------------------------------------------------------------
// 0) Weight transpose + fp16 hi/lo split: Wt*[l][n][k] = split(Wf[l][k][n])
// ---------------------------------------------------------------------------
__global__ void transpose_split_w(const float* __restrict__ Wf) {
    __shared__ float t[32][33];
    const int l  = blockIdx.z;
    const int k0 = blockIdx.y * 32, n0 = blockIdx.x * 32;
    const int tx = threadIdx.x, ty = threadIdx.y;     // 32 x 8
    const float* src = Wf + (size_t)l * DIM * DIM;
#pragma unroll
    for (int i = 0; i < 4; i++)
        t[ty + i * 8][tx] = src[(size_t)(k0 + ty + i * 8) * DIM + n0 + tx];
    __syncthreads();
#pragma unroll
    for (int i = 0; i < 4; i++) {
        float v = t[tx][ty + i * 8];                  // = Wf[k0+tx][n0+ty+i*8]
        size_t dst = (size_t)l * DIM * DIM + (size_t)(n0 + ty + i * 8) * DIM + k0 + tx;
        __half hi = __float2half_rn(v);
        g_Wth[dst] = hi;
        g_Wtl[dst] = __float2half_rn(v - __half2float(hi));
    }
}

// ---------------------------------------------------------------------------
// 1) Gather + split: Vh/Vl[row,:] = split(embed[fp[row],:])
// ---------------------------------------------------------------------------
__global__ void gather_embed(const int* __restrict__ fp,
                             const float* __restrict__ embed) {
    int row = blockIdx.x;                  // 16384 blocks, 128 threads
    int f = fp[row];
    float4 v = ((const float4*)(embed + (size_t)f * DIM))[threadIdx.x];
    size_t o = (size_t)row * DIM + threadIdx.x * 4;
    __half hx = __float2half_rn(v.x), hy = __float2half_rn(v.y);
    __half hz = __float2half_rn(v.z), hw = __float2half_rn(v.w);
    *(__half2*)(g_Vh + o)     = __halves2half2(hx, hy);
    *(__half2*)(g_Vh + o + 2) = __halves2half2(hz, hw);
    *(__half2*)(g_Vl + o)     = __halves2half2(__float2half_rn(v.x - __half2float(hx)),
                                               __float2half_rn(v.y - __half2float(hy)));
    *(__half2*)(g_Vl + o + 2) = __halves2half2(__float2half_rn(v.z - __half2float(hz)),
                                               __float2half_rn(v.w - __half2float(hw)));
}

// ---------------------------------------------------------------------------
// 2) fp16-split tensor-core GEMM with ldmatrix + cp.async double buffering
//    H = relu(V @ Wf + bf).  CTA 128x128, 8 warps of 64x32, KC=64.
//    Smem layout per operand: 128 rows x 64 halves (128B rows),
//    16B chunk index XOR-swizzled with (row & 7) -> conflict-free.
// ---------------------------------------------------------------------------
#define KC2     64
#define NCH     (DIM / KC2)            // 8 chunks
#define OPB     (128 * KC2 * 2)        // 16384 bytes per operand per stage
#define STAGEB  (4 * OPB)              // 65536 bytes
#define HG_SMEM (2 * STAGEB)           // 131072 bytes

__device__ __forceinline__ void hg_issue(
    int c, int m0, int n0, uint32_t smem_u32, int tid,
    const __half* __restrict__ Ah, const __half* __restrict__ Al,
    const __half* __restrict__ Bh, const __half* __restrict__ Bl) {
    const int s = c & 1;
    const int k0 = c * KC2;
    const uint32_t sbase = smem_u32 + s * STAGEB;
#pragma unroll
    for (int i = 0; i < 4; i++) {
        int idx = tid + i * 256;              // 0..1023 : row = idx/8, chunk = idx%8
        int r = idx >> 3, ch = idx & 7;
        uint32_t doff = (uint32_t)(r * 128 + ((ch ^ (r & 7)) * 16));
        size_t goA = (size_t)(m0 + r) * DIM + k0 + ch * 8;
        size_t goB = (size_t)(n0 + r) * DIM + k0 + ch * 8;
        CP_ASYNC16(sbase + 0 * OPB + doff, Ah + goA);
        CP_ASYNC16(sbase + 1 * OPB + doff, Al + goA);
        CP_ASYNC16(sbase + 2 * OPB + doff, Bh + goB);
        CP_ASYNC16(sbase + 3 * OPB + doff, Bl + goB);
    }
}

__global__ void __launch_bounds__(256, 1)
hgemm_split(const __half* __restrict__ Ah, const __half* __restrict__ Al,
            const __half* __restrict__ Bh, const __half* __restrict__ Bl,
            const float* __restrict__ bias, float* __restrict__ C) {
    extern __shared__ __half hsm[];
    const uint32_t smem_u32 = smem_to_u32(hsm);
    const int tid = threadIdx.x;
    const int lane = tid & 31, wid = tid >> 5;
    const int m0 = blockIdx.y * 128, n0 = blockIdx.x * 128;
    const int wm = (wid >> 2) * 64, wn = (wid & 3) * 32;
    const int g = lane >> 2, tg = lane & 3;

    // ldmatrix lane-address components: row = tileRow + (lane&15), chunk += lane>>4
    const int lrow = lane & 15, lsel = lane >> 4, lsw = lrow & 7;

    float acc[4][4][4];
#pragma unroll
    for (int i = 0; i < 4; i++)
#pragma unroll
        for (int j = 0; j < 4; j++)
#pragma unroll
            for (int r = 0; r < 4; r++) acc[i][j][r] = 0.0f;

    hg_issue(0, m0, n0, smem_u32, tid, Ah, Al, Bh, Bl);
    CP_COMMIT();

    for (int c = 0; c < NCH; c++) {
        CP_WAIT0();
        __syncthreads();
        if (c + 1 < NCH) {
            hg_issue(c + 1, m0, n0, smem_u32, tid, Ah, Al, Bh, Bl);
            CP_COMMIT();
        }
        const uint32_t sb = smem_u32 + (c & 1) * STAGEB;
        const uint32_t aH = sb, aL = sb + OPB, bH = sb + 2 * OPB, bL = sb + 3 * OPB;

#pragma unroll
        for (int ks = 0; ks < KC2 / 16; ks++) {
            const int kc0 = ks * 2;
            const uint32_t swz = (uint32_t)(((kc0 + lsel) ^ lsw) * 16);
            uint32_t a_hi[4][4], a_lo[4][4], b_hi[8], b_lo[8];

            // A hi fragments (4x ldmatrix.x4)
#pragma unroll
            for (int mf = 0; mf < 4; mf++) {
                uint32_t addr = aH + (uint32_t)((wm + mf * 16 + lrow) * 128) + swz;
                LDSM4(a_hi[mf][0], a_hi[mf][1], a_hi[mf][2], a_hi[mf][3], addr);
            }
            // B hi fragments (2x ldmatrix.x4 covering 4 n-frags)
#pragma unroll
            for (int p = 0; p < 2; p++) {
                uint32_t addr = bH + (uint32_t)((wn + p * 16 + lrow) * 128) + swz;
                LDSM4(b_hi[p * 4 + 0], b_hi[p * 4 + 1], b_hi[p * 4 + 2], b_hi[p * 4 + 3], addr);
            }
            // term 1: Ah * Bh
#pragma unroll
            for (int mf = 0; mf < 4; mf++)
#pragma unroll
                for (int nf = 0; nf < 4; nf++) {
                    int p = nf >> 1, o = nf & 1;
                    uint32_t bf[2] = { b_hi[p * 4 + o], b_hi[p * 4 + o + 2] };
                    mma16816(acc[mf][nf], a_hi[mf], bf);
                }
            // B lo ; term 3: Ah * Bl
#pragma unroll
            for (int p = 0; p < 2; p++) {
                uint32_t addr = bL + (uint32_t)((wn + p * 16 + lrow) * 128) + swz;
                LDSM4(b_lo[p * 4 + 0], b_lo[p * 4 + 1], b_lo[p * 4 + 2], b_lo[p * 4 + 3], addr);
            }
#pragma unroll
            for (int mf = 0; mf < 4; mf++)
#pragma unroll
                for (int nf = 0; nf < 4; nf++) {
                    int p = nf >> 1, o = nf & 1;
                    uint32_t bf[2] = { b_lo[p * 4 + o], b_lo[p * 4 + o + 2] };
                    mma16816(acc[mf][nf], a_hi[mf], bf);
                }
            // A lo ; term 2: Al * Bh
#pragma unroll
            for (int mf = 0; mf < 4; mf++) {
                uint32_t addr = aL + (uint32_t)((wm + mf * 16 + lrow) * 128) + swz;
                LDSM4(a_lo[mf][0], a_lo[mf][1], a_lo[mf][2], a_lo[mf][3], addr);
            }
#pragma unroll
            for (int mf = 0; mf < 4; mf++)
#pragma unroll
                for (int nf = 0; nf < 4; nf++) {
                    int p = nf >> 1, o = nf & 1;
                    uint32_t bf[2] = { b_hi[p * 4 + o], b_hi[p * 4 + o + 2] };
                    mma16816(acc[mf][nf], a_lo[mf], bf);
                }
        }
        __syncthreads();
    }

    // Epilogue: bias + relu, fp32 out
#pragma unroll
    for (int mf = 0; mf < 4; mf++) {
        int r0 = m0 + wm + mf * 16 + g;
#pragma unroll
        for (int nf = 0; nf < 4; nf++) {
            int col = n0 + wn + nf * 8 + tg * 2;
            float b0 = bias[col], b1 = bias[col + 1];
            float2 o0, o1;
            o0.x = fmaxf(acc[mf][nf][0] + b0, 0.0f);
            o0.y = fmaxf(acc[mf][nf][1] + b1, 0.0f);
            o1.x = fmaxf(acc[mf][nf][2] + b0, 0.0f);
            o1.y = fmaxf(acc[mf][nf][3] + b1, 0.0f);
            *(float2*)(C + (size_t)r0 * DIM + col) = o0;
            *(float2*)(C + (size_t)(r0 + 8) * DIM + col) = o1;
        }
    }
}

// ---------------------------------------------------------------------------
// 3) Per-molecule message passing + L2 row normalize.
//    Non-final: writes fp16 hi/lo split only.  Final: writes g_mol mean.
// ---------------------------------------------------------------------------
#define MSG_SMEM_BYTES ((NATOMS * DIM + NATOMS * NATOMS + NATOMS) * (int)sizeof(float))

template<bool FINAL>
__global__ void msg_norm_kernel(const float* __restrict__ adj) {
    extern __shared__ float sm[];
    float* h    = sm;                       // [32][512]
    float* Asub = sm + NATOMS * DIM;        // [32][32]
    float* invn = Asub + NATOMS * NATOMS;   // [32]

    const int b   = blockIdx.x;
    const int tid = threadIdx.x;            // 256 threads

    for (int i = tid; i < NATOMS * NATOMS; i += 256)
        Asub[i] = adj[(size_t)b * NATOMS * NATOMS + i];
    {
        const float4* src = (const float4*)(g_H + (size_t)b * NATOMS * DIM);
        float4* dst = (float4*)h;
#pragma unroll
        for (int i = 0; i < (NATOMS * DIM / 4) / 256; i++)
            dst[tid + i * 256] = src[tid + i * 256];
    }
    __syncthreads();

    const int d  = tid & 127;
    const int n0 = (tid >> 7) * 16;
    float out[16][4];
#pragma unroll
    for (int n = 0; n < 16; n++)
#pragma unroll
        for (int j = 0; j < 4; j++)
            out[n][j] = h[(n0 + n) * DIM + d + j * 128];

    for (int m = 0; m < NATOMS; m++) {
        float hm0 = h[m * DIM + d];
        float hm1 = h[m * DIM + d + 128];
        float hm2 = h[m * DIM + d + 256];
        float hm3 = h[m * DIM + d + 384];
#pragma unroll
        for (int n = 0; n < 16; n++) {
            float a = Asub[(n0 + n) * NATOMS + m];
            out[n][0] = fmaf(a, hm0, out[n][0]);
            out[n][1] = fmaf(a, hm1, out[n][1]);
            out[n][2] = fmaf(a, hm2, out[n][2]);
            out[n][3] = fmaf(a, hm3, out[n][3]);
        }
    }
    __syncthreads();

#pragma unroll
    for (int n = 0; n < 16; n++)
#pragma unroll
        for (int j = 0; j < 4; j++)
            h[(n0 + n) * DIM + d + j * 128] = out[n][j];
    __syncthreads();

    {
        const int w = tid >> 5, lane = tid & 31;
        for (int r = w * 4; r < w * 4 + 4; r++) {
            float ss = 0.0f;
#pragma unroll
            for (int i = 0; i < DIM / 32; i++) {
                float x = h[r * DIM + lane + i * 32];
                ss = fmaf(x, x, ss);
            }
#pragma unroll
            for (int o = 16; o; o >>= 1) ss += __shfl_xor_sync(0xFFFFFFFFu, ss, o);
            if (lane == 0) invn[r] = 1.0f / fmaxf(sqrtf(ss), 1e-12f);
        }
    }
    __syncthreads();

    if (FINAL) {
        // mean over atoms of normalized rows -> g_mol[b]
#pragma unroll
        for (int j = 0; j < 2; j++) {
            int dd = tid + j * 256;
            float s = 0.0f;
#pragma unroll
            for (int n = 0; n < NATOMS; n++)
                s = fmaf(h[n * DIM + dd], invn[n], s);
            g_mol[(size_t)b * DIM + dd] = s * (1.0f / NATOMS);
        }
    } else {
        const size_t base = (size_t)b * NATOMS * DIM;
#pragma unroll
        for (int i = 0; i < (NATOMS * DIM) / 256; i++) {
            int idx = tid + i * 256;
            float v = h[idx] * invn[idx >> 9];
            __half hi = __float2half_rn(v);
            g_Vh[base + idx] = hi;
            g_Vl[base + idx] = __float2half_rn(v - __half2float(hi));
        }
    }
}

// ---------------------------------------------------------------------------
// 4) Scalar SGEMM for the small MLP
// ---------------------------------------------------------------------------
template<int BM, int BN, int BK, int TM, int TN, bool RELU>
__global__ void sgemm_bias_kernel(const float* __restrict__ A,
                                  const float* __restrict__ B,
                                  const float* __restrict__ bias,
                                  float* __restrict__ C,
                                  int M, int N, int K) {
    constexpr int NT = (BM / TM) * (BN / TN);
    __shared__ float As[BK][BM + 4];
    __shared__ float Bs[BK][BN + 4];

    const int tid = threadIdx.x;
    constexpr int TCOLS = BN / TN;
    const int tx = tid % TCOLS;
    const int ty = tid / TCOLS;
    const int m0 = blockIdx.y * BM;
    const int n0 = blockIdx.x * BN;

    float acc[TM][TN];
#pragma unroll
    for (int i = 0; i < TM; i++)
#pragma unroll
        for (int j = 0; j < TN; j++) acc[i][j] = 0.0f;

    for (int k0 = 0; k0 < K; k0 += BK) {
        for (int i = tid; i < BM * BK / 4; i += NT) {
            int r = i / (BK / 4);
            int c = (i % (BK / 4)) * 4;
            float4 v = *(const float4*)(A + (size_t)(m0 + r) * K + k0 + c);
            As[c + 0][r] = v.x;
            As[c + 1][r] = v.y;
            As[c + 2][r] = v.z;
            As[c + 3][r] = v.w;
        }
        for (int i = tid; i < BK * BN / 4; i += NT) {
            int r = i / (BN / 4);
            int c = (i % (BN / 4)) * 4;
            *(float4*)&Bs[r][c] = *(const float4*)(B + (size_t)(k0 + r) * N + n0 + c);
        }
        __syncthreads();
#pragma unroll
        for (int k = 0; k < BK; k++) {
            float a[TM], bb[TN];
#pragma unroll
            for (int i = 0; i < TM; i++) a[i] = As[k][ty * TM + i];
#pragma unroll
            for (int j = 0; j < TN; j++) bb[j] = Bs[k][tx * TN + j];
#pragma unroll
            for (int i = 0; i < TM; i++)
#pragma unroll
                for (int j = 0; j < TN; j++)
                    acc[i][j] = fmaf(a[i], bb[j], acc[i][j]);
        }
        __syncthreads();
    }

#pragma unroll
    for (int i = 0; i < TM; i++) {
        int m = m0 + ty * TM + i;
#pragma unroll
        for (int j = 0; j < TN; j++) {
            int n = n0 + tx * TN + j;
            float v = acc[i][j] + bias[n];
            if (RELU) v = fmaxf(v, 0.0f);
            C[(size_t)m * N + n] = v;
        }
    }
}

// ---------------------------------------------------------------------------
// 5) Final projection
// ---------------------------------------------------------------------------
__global__ void final_kernel(const float* __restrict__ mol,
                             const float* __restrict__ Wp,
                             const float* __restrict__ bp,
                             float* __restrict__ out) {
    int b = blockIdx.x;
    float s = 0.0f;
    for (int d = threadIdx.x; d < DIM; d += 128)
        s = fmaf(mol[(size_t)b * DIM + d], Wp[d], s);
    __shared__ float red[4];
#pragma unroll
    for (int o = 16; o; o >>= 1) s += __shfl_down_sync(0xFFFFFFFFu, s, o);
    if ((threadIdx.x & 31) == 0) red[threadIdx.x >> 5] = s;
    __syncthreads();
    if (threadIdx.x == 0)
        out[b] = red[0] + red[1] + red[2] + red[3] + bp[0];
}

// ---------------------------------------------------------------------------
// Launcher
// ---------------------------------------------------------------------------
extern "C" void kernel_launch(void* const* d_in, const int* in_sizes, int n_in,
                              void* d_out, int out_size) {
    const int*   fp    = (const int*)  d_in[0];
    const float* adj   = (const float*)d_in[1];
    const float* embed = (const float*)d_in[2];
    const float* Wf    = (const float*)d_in[3];
    const float* bf    = (const float*)d_in[4];
    const float* Wo    = (const float*)d_in[5];
    const float* bo    = (const float*)d_in[6];
    const float* Wp    = (const float*)d_in[7];
    const float* bp    = (const float*)d_in[8];
    float* out = (float*)d_out;

    float *H, *M0, *M1;
    __half *Vh, *Vl, *Wth, *Wtl;
    cudaGetSymbolAddress((void**)&H,   g_H);
    cudaGetSymbolAddress((void**)&Vh,  g_Vh);
    cudaGetSymbolAddress((void**)&Vl,  g_Vl);
    cudaGetSymbolAddress((void**)&Wth, g_Wth);
    cudaGetSymbolAddress((void**)&Wtl, g_Wtl);
    cudaGetSymbolAddress((void**)&M0,  g_mol);
    cudaGetSymbolAddress((void**)&M1,  g_mol2);

    cudaFuncSetAttribute(msg_norm_kernel<false>,
                         cudaFuncAttributeMaxDynamicSharedMemorySize, MSG_SMEM_BYTES);
    cudaFuncSetAttribute(msg_norm_kernel<true>,
                         cudaFuncAttributeMaxDynamicSharedMemorySize, MSG_SMEM_BYTES);
    cudaFuncSetAttribute(hgemm_split,
                         cudaFuncAttributeMaxDynamicSharedMemorySize, HG_SMEM);

    transpose_split_w<<<dim3(16, 16, LHID), dim3(32, 8)>>>(Wf);
    gather_embed<<<NROWS, 128>>>(fp, embed);

    for (int l = 0; l < LHID; l++) {
        hgemm_split<<<dim3(DIM / 128, NROWS / 128), 256, HG_SMEM>>>(
            Vh, Vl,
            Wth + (size_t)l * DIM * DIM, Wtl + (size_t)l * DIM * DIM,
            bf + (size_t)l * DIM, H);
        if (l + 1 < LHID)
            msg_norm_kernel<false><<<BATCH, 256, MSG_SMEM_BYTES>>>(adj);
        else
            msg_norm_kernel<true><<<BATCH, 256, MSG_SMEM_BYTES>>>(adj);
    }

    const float* src = M0;
    float* dst = M1;
    for (int i = 0; i < LOUT; i++) {
        sgemm_bias_kernel<32, 64, 16, 2, 4, true>
            <<<dim3(DIM / 64, BATCH / 32), 256>>>(
                src, Wo + (size_t)i * DIM * DIM, bo + (size_t)i * DIM,
                dst, BATCH, DIM, DIM);
        const float* t = src; src = dst; dst = (float*)t;
    }

    final_kernel<<<BATCH, 128>>>(src, Wp, bp, out);
}

// round 8
// speedup vs baseline: 2.2831x; 1.0430x over previous
#include <cuda_runtime.h>
#include <cuda_fp16.h>
#include <cstdint>
#include <cstddef>

// Problem constants
#define BATCH   512
#define NATOMS  32
#define DIM     512
#define NROWS   (BATCH * NATOMS)     // 16384
#define LHID    6
#define LOUT    6

// ---------------------------------------------------------------------------
// Scratch (static device globals; allocation-free per harness rules)
// ---------------------------------------------------------------------------
__device__ float  g_H [(size_t)NROWS * DIM];                      // 32 MB GEMM out
__device__ __align__(16) __half g_Vh[(size_t)NROWS * DIM];        // 16 MB act hi
__device__ __align__(16) __half g_Vl[(size_t)NROWS * DIM];        // 16 MB act lo
__device__ __align__(16) __half g_Wth[(size_t)LHID * DIM * DIM];  // 3 MB W hi (K-major)
__device__ __align__(16) __half g_Wtl[(size_t)LHID * DIM * DIM];  // 3 MB W lo (K-major)
__device__ float  g_mol [(size_t)BATCH * DIM];
__device__ float  g_mol2[(size_t)BATCH * DIM];

// ---------------------------------------------------------------------------
// PTX helpers
// ---------------------------------------------------------------------------
__device__ __forceinline__ uint32_t smem_to_u32(const void* p) {
    uint32_t a;
    asm("{ .reg .u64 t; cvta.to.shared.u64 t, %1; cvt.u32.u64 %0, t; }" : "=r"(a) : "l"(p));
    return a;
}
#define CP_ASYNC16(dst, src) \
    asm volatile("cp.async.cg.shared.global [%0], [%1], 16;" :: "r"(dst), "l"(src))
#define CP_COMMIT() asm volatile("cp.async.commit_group;" ::: "memory")
#define CP_WAIT0()  asm volatile("cp.async.wait_group 0;" ::: "memory")
#define LDSM4(R0, R1, R2, R3, addr) \
    asm volatile("ldmatrix.sync.aligned.m8n8.x4.shared.b16 {%0,%1,%2,%3}, [%4];" \
        : "=r"(R0), "=r"(R1), "=r"(R2), "=r"(R3) : "r"(addr))

__device__ __forceinline__ void mma16816(float* d, const uint32_t* a, const uint32_t* b) {
    asm volatile(
        "mma.sync.aligned.m16n8k16.row.col.f32.f16.f16.f32 "
        "{%0,%1,%2,%3}, {%4,%5,%6,%7}, {%8,%9}, {%0,%1,%2,%3};"
        : "+f"(d[0]), "+f"(d[1]), "+f"(d[2]), "+f"(d[3])
        : "r"(a[0]), "r"(a[1]), "r"(a[2]), "r"(a[3]), "r"(b[0]), "r"(b[1]));
}
// fp16-accumulate variant for the small correction terms
__device__ __forceinline__ void mma16816_f16(uint32_t* d, const uint32_t* a, const uint32_t* b) {
    asm volatile(
        "mma.sync.aligned.m16n8k16.row.col.f16.f16.f16.f16 "
        "{%0,%1}, {%2,%3,%4,%5}, {%6,%7}, {%0,%1};"
        : "+r"(d[0]), "+r"(d[1])
        : "r"(a[0]), "r"(a[1]), "r"(a[2]), "r"(a[3]), "r"(b[0]), "r"(b[1]));
}

// ---------------------------------------------------------------------------
// 0) Weight transpose + fp16 hi/lo split: Wt*[l][n][k] = split(Wf[l][k][n])
// ---------------------------------------------------------------------------
__global__ void transpose_split_w(const float* __restrict__ Wf) {
    __shared__ float t[32][33];
    const int l  = blockIdx.z;
    const int k0 = blockIdx.y * 32, n0 = blockIdx.x * 32;
    const int tx = threadIdx.x, ty = threadIdx.y;     // 32 x 8
    const float* src = Wf + (size_t)l * DIM * DIM;
#pragma unroll
    for (int i = 0; i < 4; i++)
        t[ty + i * 8][tx] = src[(size_t)(k0 + ty + i * 8) * DIM + n0 + tx];
    __syncthreads();
#pragma unroll
    for (int i = 0; i < 4; i++) {
        float v = t[tx][ty + i * 8];                  // = Wf[k0+tx][n0+ty+i*8]
        size_t dst = (size_t)l * DIM * DIM + (size_t)(n0 + ty + i * 8) * DIM + k0 + tx;
        __half hi = __float2half_rn(v);
        g_Wth[dst] = hi;
        g_Wtl[dst] = __float2half_rn(v - __half2float(hi));
    }
}

// ---------------------------------------------------------------------------
// 1) Gather + split: Vh/Vl[row,:] = split(embed[fp[row],:])
// ---------------------------------------------------------------------------
__global__ void gather_embed(const int* __restrict__ fp,
                             const float* __restrict__ embed) {
    int row = blockIdx.x;                  // 16384 blocks, 128 threads
    int f = fp[row];
    float4 v = ((const float4*)(embed + (size_t)f * DIM))[threadIdx.x];
    size_t o = (size_t)row * DIM + threadIdx.x * 4;
    __half hx = __float2half_rn(v.x), hy = __float2half_rn(v.y);
    __half hz = __float2half_rn(v.z), hw = __float2half_rn(v.w);
    *(__half2*)(g_Vh + o)     = __halves2half2(hx, hy);
    *(__half2*)(g_Vh + o + 2) = __halves2half2(hz, hw);
    *(__half2*)(g_Vl + o)     = __halves2half2(__float2half_rn(v.x - __half2float(hx)),
                                               __float2half_rn(v.y - __half2float(hy)));
    *(__half2*)(g_Vl + o + 2) = __halves2half2(__float2half_rn(v.z - __half2float(hz)),
                                               __float2half_rn(v.w - __half2float(hw)));
}

// Tiny pacing kernel: shifts launch indices so ncu (-s 5) lands on hgemm_split.
__global__ void nop_kernel() {}

// ---------------------------------------------------------------------------
// 2) fp16-split tensor-core GEMM with ldmatrix + cp.async double buffering
//    H = relu(V @ Wf + bf).  CTA 128x128, 8 warps of 64x32, KC=64.
//    Term 1 (Ah*Bh): fp32 accumulate. Terms 2,3 (Al*Bh, Ah*Bl): fp16 accum
//    into a shared correction accumulator (values ~2^-12 scale -> safe).
// ---------------------------------------------------------------------------
#define KC2     64
#define NCH     (DIM / KC2)            // 8 chunks
#define OPB     (128 * KC2 * 2)        // 16384 bytes per operand per stage
#define STAGEB  (4 * OPB)              // 65536 bytes
#define HG_SMEM (2 * STAGEB)           // 131072 bytes

__device__ __forceinline__ void hg_issue(
    int c, int m0, int n0, uint32_t smem_u32, int tid,
    const __half* __restrict__ Ah, const __half* __restrict__ Al,
    const __half* __restrict__ Bh, const __half* __restrict__ Bl) {
    const int s = c & 1;
    const int k0 = c * KC2;
    const uint32_t sbase = smem_u32 + s * STAGEB;
#pragma unroll
    for (int i = 0; i < 4; i++) {
        int idx = tid + i * 256;              // 0..1023 : row = idx/8, chunk = idx%8
        int r = idx >> 3, ch = idx & 7;
        uint32_t doff = (uint32_t)(r * 128 + ((ch ^ (r & 7)) * 16));
        size_t goA = (size_t)(m0 + r) * DIM + k0 + ch * 8;
        size_t goB = (size_t)(n0 + r) * DIM + k0 + ch * 8;
        CP_ASYNC16(sbase + 0 * OPB + doff, Ah + goA);
        CP_ASYNC16(sbase + 1 * OPB + doff, Al + goA);
        CP_ASYNC16(sbase + 2 * OPB + doff, Bh + goB);
        CP_ASYNC16(sbase + 3 * OPB + doff, Bl + goB);
    }
}

__global__ void __launch_bounds__(256, 1)
hgemm_split(const __half* __restrict__ Ah, const __half* __restrict__ Al,
            const __half* __restrict__ Bh, const __half* __restrict__ Bl,
            const float* __restrict__ bias, float* __restrict__ C) {
    extern __shared__ __half hsm[];
    const uint32_t smem_u32 = smem_to_u32(hsm);
    const int tid = threadIdx.x;
    const int lane = tid & 31, wid = tid >> 5;
    const int m0 = blockIdx.y * 128, n0 = blockIdx.x * 128;
    const int wm = (wid >> 2) * 64, wn = (wid & 3) * 32;
    const int g = lane >> 2, tg = lane & 3;

    const int lrow = lane & 15, lsel = lane >> 4, lsw = lrow & 7;

    float acc[4][4][4];
    uint32_t accc[4][4][2];                   // fp16 correction accumulators
#pragma unroll
    for (int i = 0; i < 4; i++)
#pragma unroll
        for (int j = 0; j < 4; j++) {
#pragma unroll
            for (int r = 0; r < 4; r++) acc[i][j][r] = 0.0f;
            accc[i][j][0] = 0u; accc[i][j][1] = 0u;
        }

    hg_issue(0, m0, n0, smem_u32, tid, Ah, Al, Bh, Bl);
    CP_COMMIT();

    for (int c = 0; c < NCH; c++) {
        CP_WAIT0();
        __syncthreads();
        if (c + 1 < NCH) {
            hg_issue(c + 1, m0, n0, smem_u32, tid, Ah, Al, Bh, Bl);
            CP_COMMIT();
        }
        const uint32_t sb = smem_u32 + (c & 1) * STAGEB;
        const uint32_t aH = sb, aL = sb + OPB, bH = sb + 2 * OPB, bL = sb + 3 * OPB;

#pragma unroll
        for (int ks = 0; ks < KC2 / 16; ks++) {
            const int kc0 = ks * 2;
            const uint32_t swz = (uint32_t)(((kc0 + lsel) ^ lsw) * 16);
            uint32_t a_hi[4][4], a_lo[4][4], b_hi[8], b_lo[8];

#pragma unroll
            for (int mf = 0; mf < 4; mf++) {
                uint32_t addr = aH + (uint32_t)((wm + mf * 16 + lrow) * 128) + swz;
                LDSM4(a_hi[mf][0], a_hi[mf][1], a_hi[mf][2], a_hi[mf][3], addr);
            }
#pragma unroll
            for (int p = 0; p < 2; p++) {
                uint32_t addr = bH + (uint32_t)((wn + p * 16 + lrow) * 128) + swz;
                LDSM4(b_hi[p * 4 + 0], b_hi[p * 4 + 1], b_hi[p * 4 + 2], b_hi[p * 4 + 3], addr);
            }
            // term 1: Ah * Bh  (fp32 accumulate)
#pragma unroll
            for (int mf = 0; mf < 4; mf++)
#pragma unroll
                for (int nf = 0; nf < 4; nf++) {
                    int p = nf >> 1, o = nf & 1;
                    uint32_t bf[2] = { b_hi[p * 4 + o], b_hi[p * 4 + o + 2] };
                    mma16816(acc[mf][nf], a_hi[mf], bf);
                }
            // term 3: Ah * Bl (fp16 accumulate)
#pragma unroll
            for (int p = 0; p < 2; p++) {
                uint32_t addr = bL + (uint32_t)((wn + p * 16 + lrow) * 128) + swz;
                LDSM4(b_lo[p * 4 + 0], b_lo[p * 4 + 1], b_lo[p * 4 + 2], b_lo[p * 4 + 3], addr);
            }
#pragma unroll
            for (int mf = 0; mf < 4; mf++)
#pragma unroll
                for (int nf = 0; nf < 4; nf++) {
                    int p = nf >> 1, o = nf & 1;
                    uint32_t bf[2] = { b_lo[p * 4 + o], b_lo[p * 4 + o + 2] };
                    mma16816_f16(accc[mf][nf], a_hi[mf], bf);
                }
            // term 2: Al * Bh (fp16 accumulate)
#pragma unroll
            for (int mf = 0; mf < 4; mf++) {
                uint32_t addr = aL + (uint32_t)((wm + mf * 16 + lrow) * 128) + swz;
                LDSM4(a_lo[mf][0], a_lo[mf][1], a_lo[mf][2], a_lo[mf][3], addr);
            }
#pragma unroll
            for (int mf = 0; mf < 4; mf++)
#pragma unroll
                for (int nf = 0; nf < 4; nf++) {
                    int p = nf >> 1, o = nf & 1;
                    uint32_t bf[2] = { b_hi[p * 4 + o], b_hi[p * 4 + o + 2] };
                    mma16816_f16(accc[mf][nf], a_lo[mf], bf);
                }
        }
        __syncthreads();
    }

    // Epilogue: acc + correction + bias, relu, fp32 out
#pragma unroll
    for (int mf = 0; mf < 4; mf++) {
        int r0 = m0 + wm + mf * 16 + g;
#pragma unroll
        for (int nf = 0; nf < 4; nf++) {
            int col = n0 + wn + nf * 8 + tg * 2;
            float b0 = bias[col], b1 = bias[col + 1];
            __half2 c01 = *(__half2*)&accc[mf][nf][0];
            __half2 c23 = *(__half2*)&accc[mf][nf][1];
            float2 o0, o1;
            o0.x = fmaxf(acc[mf][nf][0] + __low2float(c01)  + b0, 0.0f);
            o0.y = fmaxf(acc[mf][nf][1] + __high2float(c01) + b1, 0.0f);
            o1.x = fmaxf(acc[mf][nf][2] + __low2float(c23)  + b0, 0.0f);
            o1.y = fmaxf(acc[mf][nf][3] + __high2float(c23) + b1, 0.0f);
            *(float2*)(C + (size_t)r0 * DIM + col) = o0;
            *(float2*)(C + (size_t)(r0 + 8) * DIM + col) = o1;
        }
    }
}

// ---------------------------------------------------------------------------
// 3) Per-molecule message passing + L2 row normalize.
//    Thread tile: 16 atoms x 4 CONTIGUOUS dims; m blocked by 4 so all smem
//    traffic is LDS.128 (hm float4, Asub rows float4).
// ---------------------------------------------------------------------------
#define MSG_SMEM_BYTES ((NATOMS * DIM + NATOMS * NATOMS + NATOMS) * (int)sizeof(float))

template<bool FINAL>
__global__ void msg_norm_kernel(const float* __restrict__ adj) {
    extern __shared__ float sm[];
    float* h    = sm;                       // [32][512]
    float* Asub = sm + NATOMS * DIM;        // [32][32]
    float* invn = Asub + NATOMS * NATOMS;   // [32]

    const int b   = blockIdx.x;
    const int tid = threadIdx.x;            // 256 threads

    for (int i = tid; i < NATOMS * NATOMS; i += 256)
        Asub[i] = adj[(size_t)b * NATOMS * NATOMS + i];
    {
        const float4* src = (const float4*)(g_H + (size_t)b * NATOMS * DIM);
        float4* dst = (float4*)h;
#pragma unroll
        for (int i = 0; i < (NATOMS * DIM / 4) / 256; i++)
            dst[tid + i * 256] = src[tid + i * 256];
    }
    __syncthreads();

    const int d0 = (tid & 127) * 4;         // 4 contiguous dims
    const int n0 = (tid >> 7) * 16;         // atom half
    float4 out[16];
#pragma unroll
    for (int n = 0; n < 16; n++)
        out[n] = *(float4*)&h[(n0 + n) * DIM + d0];

#pragma unroll
    for (int m4 = 0; m4 < NATOMS / 4; m4++) {
        float4 hm[4];
#pragma unroll
        for (int i = 0; i < 4; i++)
            hm[i] = *(float4*)&h[(m4 * 4 + i) * DIM + d0];
#pragma unroll
        for (int n = 0; n < 16; n++) {
            float4 a4 = *(float4*)&Asub[(n0 + n) * NATOMS + m4 * 4];
            out[n].x = fmaf(a4.x, hm[0].x, out[n].x);
            out[n].y = fmaf(a4.x, hm[0].y, out[n].y);
            out[n].z = fmaf(a4.x, hm[0].z, out[n].z);
            out[n].w = fmaf(a4.x, hm[0].w, out[n].w);
            out[n].x = fmaf(a4.y, hm[1].x, out[n].x);
            out[n].y = fmaf(a4.y, hm[1].y, out[n].y);
            out[n].z = fmaf(a4.y, hm[1].z, out[n].z);
            out[n].w = fmaf(a4.y, hm[1].w, out[n].w);
            out[n].x = fmaf(a4.z, hm[2].x, out[n].x);
            out[n].y = fmaf(a4.z, hm[2].y, out[n].y);
            out[n].z = fmaf(a4.z, hm[2].z, out[n].z);
            out[n].w = fmaf(a4.z, hm[2].w, out[n].w);
            out[n].x = fmaf(a4.w, hm[3].x, out[n].x);
            out[n].y = fmaf(a4.w, hm[3].y, out[n].y);
            out[n].z = fmaf(a4.w, hm[3].z, out[n].z);
            out[n].w = fmaf(a4.w, hm[3].w, out[n].w);
        }
    }
    __syncthreads();   // all reads of h complete before in-place overwrite

#pragma unroll
    for (int n = 0; n < 16; n++)
        *(float4*)&h[(n0 + n) * DIM + d0] = out[n];
    __syncthreads();

    {
        const int w = tid >> 5, lane = tid & 31;
        for (int r = w * 4; r < w * 4 + 4; r++) {
            float ss = 0.0f;
#pragma unroll
            for (int i = 0; i < DIM / 32; i++) {
                float x = h[r * DIM + lane + i * 32];
                ss = fmaf(x, x, ss);
            }
#pragma unroll
            for (int o = 16; o; o >>= 1) ss += __shfl_xor_sync(0xFFFFFFFFu, ss, o);
            if (lane == 0) invn[r] = 1.0f / fmaxf(sqrtf(ss), 1e-12f);
        }
    }
    __syncthreads();

    if (FINAL) {
        // mean over atoms of normalized rows -> g_mol[b]
#pragma unroll
        for (int j = 0; j < 2; j++) {
            int dd = tid + j * 256;
            float s = 0.0f;
#pragma unroll
            for (int n = 0; n < NATOMS; n++)
                s = fmaf(h[n * DIM + dd], invn[n], s);
            g_mol[(size_t)b * DIM + dd] = s * (1.0f / NATOMS);
        }
    } else {
        const size_t base = (size_t)b * NATOMS * DIM;
#pragma unroll
        for (int i = 0; i < (NATOMS * DIM) / 256; i++) {
            int idx = tid + i * 256;
            float v = h[idx] * invn[idx >> 9];
            __half hi = __float2half_rn(v);
            g_Vh[base + idx] = hi;
            g_Vl[base + idx] = __float2half_rn(v - __half2float(hi));
        }
    }
}

// ---------------------------------------------------------------------------
// 4) Scalar SGEMM for the small MLP
// ---------------------------------------------------------------------------
template<int BM, int BN, int BK, int TM, int TN, bool RELU>
__global__ void sgemm_bias_kernel(const float* __restrict__ A,
                                  const float* __restrict__ B,
                                  const float* __restrict__ bias,
                                  float* __restrict__ C,
                                  int M, int N, int K) {
    constexpr int NT = (BM / TM) * (BN / TN);
    __shared__ float As[BK][BM + 4];
    __shared__ float Bs[BK][BN + 4];

    const int tid = threadIdx.x;
    constexpr int TCOLS = BN / TN;
    const int tx = tid % TCOLS;
    const int ty = tid / TCOLS;
    const int m0 = blockIdx.y * BM;
    const int n0 = blockIdx.x * BN;

    float acc[TM][TN];
#pragma unroll
    for (int i = 0; i < TM; i++)
#pragma unroll
        for (int j = 0; j < TN; j++) acc[i][j] = 0.0f;

    for (int k0 = 0; k0 < K; k0 += BK) {
        for (int i = tid; i < BM * BK / 4; i += NT) {
            int r = i / (BK / 4);
            int c = (i % (BK / 4)) * 4;
            float4 v = *(const float4*)(A + (size_t)(m0 + r) * K + k0 + c);
            As[c + 0][r] = v.x;
            As[c + 1][r] = v.y;
            As[c + 2][r] = v.z;
            As[c + 3][r] = v.w;
        }
        for (int i = tid; i < BK * BN / 4; i += NT) {
            int r = i / (BN / 4);
            int c = (i % (BN / 4)) * 4;
            *(float4*)&Bs[r][c] = *(const float4*)(B + (size_t)(k0 + r) * N + n0 + c);
        }
        __syncthreads();
#pragma unroll
        for (int k = 0; k < BK; k++) {
            float a[TM], bb[TN];
#pragma unroll
            for (int i = 0; i < TM; i++) a[i] = As[k][ty * TM + i];
#pragma unroll
            for (int j = 0; j < TN; j++) bb[j] = Bs[k][tx * TN + j];
#pragma unroll
            for (int i = 0; i < TM; i++)
#pragma unroll
                for (int j = 0; j < TN; j++)
                    acc[i][j] = fmaf(a[i], bb[j], acc[i][j]);
        }
        __syncthreads();
    }

#pragma unroll
    for (int i = 0; i < TM; i++) {
        int m = m0 + ty * TM + i;
#pragma unroll
        for (int j = 0; j < TN; j++) {
            int n = n0 + tx * TN + j;
            float v = acc[i][j] + bias[n];
            if (RELU) v = fmaxf(v, 0.0f);
            C[(size_t)m * N + n] = v;
        }
    }
}

// ---------------------------------------------------------------------------
// 5) Final projection
// ---------------------------------------------------------------------------
__global__ void final_kernel(const float* __restrict__ mol,
                             const float* __restrict__ Wp,
                             const float* __restrict__ bp,
                             float* __restrict__ out) {
    int b = blockIdx.x;
    float s = 0.0f;
    for (int d = threadIdx.x; d < DIM; d += 128)
        s = fmaf(mol[(size_t)b * DIM + d], Wp[d], s);
    __shared__ float red[4];
#pragma unroll
    for (int o = 16; o; o >>= 1) s += __shfl_down_sync(0xFFFFFFFFu, s, o);
    if ((threadIdx.x & 31) == 0) red[threadIdx.x >> 5] = s;
    __syncthreads();
    if (threadIdx.x == 0)
        out[b] = red[0] + red[1] + red[2] + red[3] + bp[0];
}

// ---------------------------------------------------------------------------
// Launcher
// ---------------------------------------------------------------------------
extern "C" void kernel_launch(void* const* d_in, const int* in_sizes, int n_in,
                              void* d_out, int out_size) {
    const int*   fp    = (const int*)  d_in[0];
    const float* adj   = (const float*)d_in[1];
    const float* embed = (const float*)d_in[2];
    const float* Wf    = (const float*)d_in[3];
    const float* bf    = (const float*)d_in[4];
    const float* Wo    = (const float*)d_in[5];
    const float* bo    = (const float*)d_in[6];
    const float* Wp    = (const float*)d_in[7];
    const float* bp    = (const float*)d_in[8];
    float* out = (float*)d_out;

    float *H, *M0, *M1;
    __half *Vh, *Vl, *Wth, *Wtl;
    cudaGetSymbolAddress((void**)&H,   g_H);
    cudaGetSymbolAddress((void**)&Vh,  g_Vh);
    cudaGetSymbolAddress((void**)&Vl,  g_Vl);
    cudaGetSymbolAddress((void**)&Wth, g_Wth);
    cudaGetSymbolAddress((void**)&Wtl, g_Wtl);
    cudaGetSymbolAddress((void**)&M0,  g_mol);
    cudaGetSymbolAddress((void**)&M1,  g_mol2);

    cudaFuncSetAttribute(msg_norm_kernel<false>,
                         cudaFuncAttributeMaxDynamicSharedMemorySize, MSG_SMEM_BYTES);
    cudaFuncSetAttribute(msg_norm_kernel<true>,
                         cudaFuncAttributeMaxDynamicSharedMemorySize, MSG_SMEM_BYTES);
    cudaFuncSetAttribute(hgemm_split,
                         cudaFuncAttributeMaxDynamicSharedMemorySize, HG_SMEM);

    transpose_split_w<<<dim3(16, 16, LHID), dim3(32, 8)>>>(Wf);   // launch 0
    gather_embed<<<NROWS, 128>>>(fp, embed);                      // launch 1
    nop_kernel<<<1, 32>>>();                                      // launch 2 (ncu aligns idx5 = hgemm)

    for (int l = 0; l < LHID; l++) {
        hgemm_split<<<dim3(DIM / 128, NROWS / 128), 256, HG_SMEM>>>(
            Vh, Vl,
            Wth + (size_t)l * DIM * DIM, Wtl + (size_t)l * DIM * DIM,
            bf + (size_t)l * DIM, H);
        if (l + 1 < LHID)
            msg_norm_kernel<false><<<BATCH, 256, MSG_SMEM_BYTES>>>(adj);
        else
            msg_norm_kernel<true><<<BATCH, 256, MSG_SMEM_BYTES>>>(adj);
    }

    const float* src = M0;
    float* dst = M1;
    for (int i = 0; i < LOUT; i++) {
        sgemm_bias_kernel<32, 64, 16, 2, 4, true>
            <<<dim3(DIM / 64, BATCH / 32), 256>>>(
                src, Wo + (size_t)i * DIM * DIM, bo + (size_t)i * DIM,
                dst, BATCH, DIM, DIM);
        const float* t = src; src = dst; dst = (float*)t;
    }

    final_kernel<<<BATCH, 128>>>(src, Wp, bp, out);
}

// round 10
// speedup vs baseline: 2.3193x; 1.0158x over previous
#include <cuda_runtime.h>
#include <cuda_fp16.h>
#include <cstdint>
#include <cstddef>

// Problem constants
#define BATCH   512
#define NATOMS  32
#define DIM     512
#define NROWS   (BATCH * NATOMS)     // 16384
#define LHID    6
#define LOUT    6

// ---------------------------------------------------------------------------
// Scratch (static device globals; allocation-free per harness rules)
// ---------------------------------------------------------------------------
__device__ float  g_H [(size_t)NROWS * DIM];                      // 32 MB GEMM out
__device__ __align__(16) __half g_Vh[(size_t)NROWS * DIM];        // 16 MB act hi
__device__ __align__(16) __half g_Vl[(size_t)NROWS * DIM];        // 16 MB act lo
__device__ __align__(16) __half g_Wth[(size_t)LHID * DIM * DIM];  // 3 MB W hi (K-major)
__device__ __align__(16) __half g_Wtl[(size_t)LHID * DIM * DIM];  // 3 MB W lo (K-major)
__device__ float  g_mol [(size_t)BATCH * DIM];
__device__ float  g_mol2[(size_t)BATCH * DIM];

// ---------------------------------------------------------------------------
// PTX helpers
// ---------------------------------------------------------------------------
__device__ __forceinline__ uint32_t smem_to_u32(const void* p) {
    uint32_t a;
    asm("{ .reg .u64 t; cvta.to.shared.u64 t, %1; cvt.u32.u64 %0, t; }" : "=r"(a) : "l"(p));
    return a;
}
#define CP_ASYNC16(dst, src) \
    asm volatile("cp.async.cg.shared.global [%0], [%1], 16;" :: "r"(dst), "l"(src))
#define CP_COMMIT() asm volatile("cp.async.commit_group;" ::: "memory")
#define CP_WAIT0()  asm volatile("cp.async.wait_group 0;" ::: "memory")
#define LDSM4(R0, R1, R2, R3, addr) \
    asm volatile("ldmatrix.sync.aligned.m8n8.x4.shared.b16 {%0,%1,%2,%3}, [%4];" \
        : "=r"(R0), "=r"(R1), "=r"(R2), "=r"(R3) : "r"(addr))

__device__ __forceinline__ void mma16816(float* d, const uint32_t* a, const uint32_t* b) {
    asm volatile(
        "mma.sync.aligned.m16n8k16.row.col.f32.f16.f16.f32 "
        "{%0,%1,%2,%3}, {%4,%5,%6,%7}, {%8,%9}, {%0,%1,%2,%3};"
        : "+f"(d[0]), "+f"(d[1]), "+f"(d[2]), "+f"(d[3])
        : "r"(a[0]), "r"(a[1]), "r"(a[2]), "r"(a[3]), "r"(b[0]), "r"(b[1]));
}
// fp16-accumulate variant for the small correction terms
__device__ __forceinline__ void mma16816_f16(uint32_t* d, const uint32_t* a, const uint32_t* b) {
    asm volatile(
        "mma.sync.aligned.m16n8k16.row.col.f16.f16.f16.f16 "
        "{%0,%1}, {%2,%3,%4,%5}, {%6,%7}, {%0,%1};"
        : "+r"(d[0]), "+r"(d[1])
        : "r"(a[0]), "r"(a[1]), "r"(a[2]), "r"(a[3]), "r"(b[0]), "r"(b[1]));
}

// ---------------------------------------------------------------------------
// 0) Weight transpose + fp16 hi/lo split: Wt*[l][n][k] = split(Wf[l][k][n])
// ---------------------------------------------------------------------------
__global__ void transpose_split_w(const float* __restrict__ Wf) {
    __shared__ float t[32][33];
    const int l  = blockIdx.z;
    const int k0 = blockIdx.y * 32, n0 = blockIdx.x * 32;
    const int tx = threadIdx.x, ty = threadIdx.y;     // 32 x 8
    const float* src = Wf + (size_t)l * DIM * DIM;
#pragma unroll
    for (int i = 0; i < 4; i++)
        t[ty + i * 8][tx] = src[(size_t)(k0 + ty + i * 8) * DIM + n0 + tx];
    __syncthreads();
#pragma unroll
    for (int i = 0; i < 4; i++) {
        float v = t[tx][ty + i * 8];                  // = Wf[k0+tx][n0+ty+i*8]
        size_t dst = (size_t)l * DIM * DIM + (size_t)(n0 + ty + i * 8) * DIM + k0 + tx;
        __half hi = __float2half_rn(v);
        g_Wth[dst] = hi;
        g_Wtl[dst] = __float2half_rn(v - __half2float(hi));
    }
}

// ---------------------------------------------------------------------------
// 1) Gather + split: Vh/Vl[row,:] = split(embed[fp[row],:])
// ---------------------------------------------------------------------------
__global__ void gather_embed(const int* __restrict__ fp,
                             const float* __restrict__ embed) {
    int row = blockIdx.x;                  // 16384 blocks, 128 threads
    int f = fp[row];
    float4 v = ((const float4*)(embed + (size_t)f * DIM))[threadIdx.x];
    size_t o = (size_t)row * DIM + threadIdx.x * 4;
    __half hx = __float2half_rn(v.x), hy = __float2half_rn(v.y);
    __half hz = __float2half_rn(v.z), hw = __float2half_rn(v.w);
    *(__half2*)(g_Vh + o)     = __halves2half2(hx, hy);
    *(__half2*)(g_Vh + o + 2) = __halves2half2(hz, hw);
    *(__half2*)(g_Vl + o)     = __halves2half2(__float2half_rn(v.x - __half2float(hx)),
                                               __float2half_rn(v.y - __half2float(hy)));
    *(__half2*)(g_Vl + o + 2) = __halves2half2(__float2half_rn(v.z - __half2float(hz)),
                                               __float2half_rn(v.w - __half2float(hw)));
}

// Tiny pacing kernel: shifts launch indices so ncu (-s 5) lands on hgemm_split.
__global__ void nop_kernel() {}

// ---------------------------------------------------------------------------
// 2) fp16-split tensor-core GEMM with ldmatrix + cp.async double buffering.
//    H = relu(V @ Wf + bf).  CTA 128x128, 16 warps of 32x32, KC=64.
//    Term 1 (Ah*Bh): fp32 accumulate. Terms 2,3: fp16 accumulate.
// ---------------------------------------------------------------------------
#define KC2     64
#define NCH     (DIM / KC2)            // 8 chunks
#define OPB     (128 * KC2 * 2)        // 16384 bytes per operand per stage
#define STAGEB  (4 * OPB)              // 65536 bytes
#define HG_SMEM (2 * STAGEB)           // 131072 bytes
#define HG_THREADS 512

__device__ __forceinline__ void hg_issue(
    int c, int m0, int n0, uint32_t smem_u32, int tid,
    const __half* __restrict__ Ah, const __half* __restrict__ Al,
    const __half* __restrict__ Bh, const __half* __restrict__ Bl) {
    const int s = c & 1;
    const int k0 = c * KC2;
    const uint32_t sbase = smem_u32 + s * STAGEB;
#pragma unroll
    for (int i = 0; i < 2; i++) {
        int idx = tid + i * HG_THREADS;       // 0..1023 : row = idx/8, chunk = idx%8
        int r = idx >> 3, ch = idx & 7;
        uint32_t doff = (uint32_t)(r * 128 + ((ch ^ (r & 7)) * 16));
        size_t goA = (size_t)(m0 + r) * DIM + k0 + ch * 8;
        size_t goB = (size_t)(n0 + r) * DIM + k0 + ch * 8;
        CP_ASYNC16(sbase + 0 * OPB + doff, Ah + goA);
        CP_ASYNC16(sbase + 1 * OPB + doff, Al + goA);
        CP_ASYNC16(sbase + 2 * OPB + doff, Bh + goB);
        CP_ASYNC16(sbase + 3 * OPB + doff, Bl + goB);
    }
}

__global__ void __launch_bounds__(HG_THREADS, 1)
hgemm_split(const __half* __restrict__ Ah, const __half* __restrict__ Al,
            const __half* __restrict__ Bh, const __half* __restrict__ Bl,
            const float* __restrict__ bias, float* __restrict__ C) {
    extern __shared__ __half hsm[];
    const uint32_t smem_u32 = smem_to_u32(hsm);
    const int tid = threadIdx.x;
    const int lane = tid & 31, wid = tid >> 5;       // 16 warps
    const int m0 = blockIdx.y * 128, n0 = blockIdx.x * 128;
    const int wm = (wid >> 2) * 32, wn = (wid & 3) * 32;   // 4x4 warp grid, 32x32 tiles
    const int g = lane >> 2, tg = lane & 3;

    const int lrow = lane & 15, lsel = lane >> 4, lsw = lrow & 7;

    // Warp-constant LDSM row-address components (only swz varies per ks).
    const uint32_t rA0 = (uint32_t)((wm + lrow) * 128);
    const uint32_t rA1 = (uint32_t)((wm + 16 + lrow) * 128);
    const uint32_t rB0 = (uint32_t)((wn + lrow) * 128);
    const uint32_t rB1 = (uint32_t)((wn + 16 + lrow) * 128);

    float acc[2][4][4];
    uint32_t accc[2][4][2];                   // fp16 correction accumulators
#pragma unroll
    for (int i = 0; i < 2; i++)
#pragma unroll
        for (int j = 0; j < 4; j++) {
#pragma unroll
            for (int r = 0; r < 4; r++) acc[i][j][r] = 0.0f;
            accc[i][j][0] = 0u; accc[i][j][1] = 0u;
        }

    hg_issue(0, m0, n0, smem_u32, tid, Ah, Al, Bh, Bl);
    CP_COMMIT();

    for (int c = 0; c < NCH; c++) {
        CP_WAIT0();
        __syncthreads();
        if (c + 1 < NCH) {
            hg_issue(c + 1, m0, n0, smem_u32, tid, Ah, Al, Bh, Bl);
            CP_COMMIT();
        }
        const uint32_t sb = smem_u32 + (c & 1) * STAGEB;
        const uint32_t aH = sb, aL = sb + OPB, bH = sb + 2 * OPB, bL = sb + 3 * OPB;

#pragma unroll
        for (int ks = 0; ks < KC2 / 16; ks++) {
            const uint32_t swz = (uint32_t)((((ks * 2) + lsel) ^ lsw) * 16);
            uint32_t a_hi[2][4], a_lo[2][4], b_hi[2][4], b_lo[2][4];

            LDSM4(a_hi[0][0], a_hi[0][1], a_hi[0][2], a_hi[0][3], aH + rA0 + swz);
            LDSM4(a_hi[1][0], a_hi[1][1], a_hi[1][2], a_hi[1][3], aH + rA1 + swz);
            LDSM4(b_hi[0][0], b_hi[0][1], b_hi[0][2], b_hi[0][3], bH + rB0 + swz);
            LDSM4(b_hi[1][0], b_hi[1][1], b_hi[1][2], b_hi[1][3], bH + rB1 + swz);
            // term 1: Ah * Bh (fp32 accumulate)
#pragma unroll
            for (int mf = 0; mf < 2; mf++)
#pragma unroll
                for (int nf = 0; nf < 4; nf++) {
                    int p = nf >> 1, o = nf & 1;
                    uint32_t bf[2] = { b_hi[p][o], b_hi[p][o + 2] };
                    mma16816(acc[mf][nf], a_hi[mf], bf);
                }
            // term 3: Ah * Bl (fp16 accumulate)
            LDSM4(b_lo[0][0], b_lo[0][1], b_lo[0][2], b_lo[0][3], bL + rB0 + swz);
            LDSM4(b_lo[1][0], b_lo[1][1], b_lo[1][2], b_lo[1][3], bL + rB1 + swz);
#pragma unroll
            for (int mf = 0; mf < 2; mf++)
#pragma unroll
                for (int nf = 0; nf < 4; nf++) {
                    int p = nf >> 1, o = nf & 1;
                    uint32_t bf[2] = { b_lo[p][o], b_lo[p][o + 2] };
                    mma16816_f16(accc[mf][nf], a_hi[mf], bf);
                }
            // term 2: Al * Bh (fp16 accumulate)
            LDSM4(a_lo[0][0], a_lo[0][1], a_lo[0][2], a_lo[0][3], aL + rA0 + swz);
            LDSM4(a_lo[1][0], a_lo[1][1], a_lo[1][2], a_lo[1][3], aL + rA1 + swz);
#pragma unroll
            for (int mf = 0; mf < 2; mf++)
#pragma unroll
                for (int nf = 0; nf < 4; nf++) {
                    int p = nf >> 1, o = nf & 1;
                    uint32_t bf[2] = { b_hi[p][o], b_hi[p][o + 2] };
                    mma16816_f16(accc[mf][nf], a_lo[mf], bf);
                }
        }
        __syncthreads();
    }

    // Epilogue: acc + correction + bias, relu, fp32 out
#pragma unroll
    for (int mf = 0; mf < 2; mf++) {
        int r0 = m0 + wm + mf * 16 + g;
#pragma unroll
        for (int nf = 0; nf < 4; nf++) {
            int col = n0 + wn + nf * 8 + tg * 2;
            float b0 = bias[col], b1 = bias[col + 1];
            __half2 c01 = *(__half2*)&accc[mf][nf][0];
            __half2 c23 = *(__half2*)&accc[mf][nf][1];
            float2 o0, o1;
            o0.x = fmaxf(acc[mf][nf][0] + __low2float(c01)  + b0, 0.0f);
            o0.y = fmaxf(acc[mf][nf][1] + __high2float(c01) + b1, 0.0f);
            o1.x = fmaxf(acc[mf][nf][2] + __low2float(c23)  + b0, 0.0f);
            o1.y = fmaxf(acc[mf][nf][3] + __high2float(c23) + b1, 0.0f);
            *(float2*)(C + (size_t)r0 * DIM + col) = o0;
            *(float2*)(C + (size_t)(r0 + 8) * DIM + col) = o1;
        }
    }
}

// ---------------------------------------------------------------------------
// 3) Per-molecule message passing + L2 row normalize.
// ---------------------------------------------------------------------------
#define MSG_SMEM_BYTES ((NATOMS * DIM + NATOMS * NATOMS + NATOMS) * (int)sizeof(float))

template<bool FINAL>
__global__ void msg_norm_kernel(const float* __restrict__ adj) {
    extern __shared__ float sm[];
    float* h    = sm;                       // [32][512]
    float* Asub = sm + NATOMS * DIM;        // [32][32]
    float* invn = Asub + NATOMS * NATOMS;   // [32]

    const int b   = blockIdx.x;
    const int tid = threadIdx.x;            // 256 threads

    for (int i = tid; i < NATOMS * NATOMS; i += 256)
        Asub[i] = adj[(size_t)b * NATOMS * NATOMS + i];
    {
        const float4* src = (const float4*)(g_H + (size_t)b * NATOMS * DIM);
        float4* dst = (float4*)h;
#pragma unroll
        for (int i = 0; i < (NATOMS * DIM / 4) / 256; i++)
            dst[tid + i * 256] = src[tid + i * 256];
    }
    __syncthreads();

    const int d0 = (tid & 127) * 4;         // 4 contiguous dims
    const int n0 = (tid >> 7) * 16;         // atom half
    float4 out[16];
#pragma unroll
    for (int n = 0; n < 16; n++)
        out[n] = *(float4*)&h[(n0 + n) * DIM + d0];

#pragma unroll
    for (int m4 = 0; m4 < NATOMS / 4; m4++) {
        float4 hm[4];
#pragma unroll
        for (int i = 0; i < 4; i++)
            hm[i] = *(float4*)&h[(m4 * 4 + i) * DIM + d0];
#pragma unroll
        for (int n = 0; n < 16; n++) {
            float4 a4 = *(float4*)&Asub[(n0 + n) * NATOMS + m4 * 4];
            out[n].x = fmaf(a4.x, hm[0].x, out[n].x);
            out[n].y = fmaf(a4.x, hm[0].y, out[n].y);
            out[n].z = fmaf(a4.x, hm[0].z, out[n].z);
            out[n].w = fmaf(a4.x, hm[0].w, out[n].w);
            out[n].x = fmaf(a4.y, hm[1].x, out[n].x);
            out[n].y = fmaf(a4.y, hm[1].y, out[n].y);
            out[n].z = fmaf(a4.y, hm[1].z, out[n].z);
            out[n].w = fmaf(a4.y, hm[1].w, out[n].w);
            out[n].x = fmaf(a4.z, hm[2].x, out[n].x);
            out[n].y = fmaf(a4.z, hm[2].y, out[n].y);
            out[n].z = fmaf(a4.z, hm[2].z, out[n].z);
            out[n].w = fmaf(a4.z, hm[2].w, out[n].w);
            out[n].x = fmaf(a4.w, hm[3].x, out[n].x);
            out[n].y = fmaf(a4.w, hm[3].y, out[n].y);
            out[n].z = fmaf(a4.w, hm[3].z, out[n].z);
            out[n].w = fmaf(a4.w, hm[3].w, out[n].w);
        }
    }
    __syncthreads();   // all reads of h complete before in-place overwrite

#pragma unroll
    for (int n = 0; n < 16; n++)
        *(float4*)&h[(n0 + n) * DIM + d0] = out[n];
    __syncthreads();

    {
        const int w = tid >> 5, lane = tid & 31;
        for (int r = w * 4; r < w * 4 + 4; r++) {
            float ss = 0.0f;
#pragma unroll
            for (int i = 0; i < DIM / 32; i++) {
                float x = h[r * DIM + lane + i * 32];
                ss = fmaf(x, x, ss);
            }
#pragma unroll
            for (int o = 16; o; o >>= 1) ss += __shfl_xor_sync(0xFFFFFFFFu, ss, o);
            if (lane == 0) invn[r] = 1.0f / fmaxf(sqrtf(ss), 1e-12f);
        }
    }
    __syncthreads();

    if (FINAL) {
#pragma unroll
        for (int j = 0; j < 2; j++) {
            int dd = tid + j * 256;
            float s = 0.0f;
#pragma unroll
            for (int n = 0; n < NATOMS; n++)
                s = fmaf(h[n * DIM + dd], invn[n], s);
            g_mol[(size_t)b * DIM + dd] = s * (1.0f / NATOMS);
        }
    } else {
        const size_t base = (size_t)b * NATOMS * DIM;
#pragma unroll
        for (int i = 0; i < (NATOMS * DIM) / 256; i++) {
            int idx = tid + i * 256;
            float v = h[idx] * invn[idx >> 9];
            __half hi = __float2half_rn(v);
            g_Vh[base + idx] = hi;
            g_Vl[base + idx] = __float2half_rn(v - __half2float(hi));
        }
    }
}

// ---------------------------------------------------------------------------
// 4) Scalar SGEMM for the small MLP
// ---------------------------------------------------------------------------
template<int BM, int BN, int BK, int TM, int TN, bool RELU>
__global__ void sgemm_bias_kernel(const float* __restrict__ A,
                                  const float* __restrict__ B,
                                  const float* __restrict__ bias,
                                  float* __restrict__ C,
                                  int M, int N, int K) {
    constexpr int NT = (BM / TM) * (BN / TN);
    __shared__ float As[BK][BM + 4];
    __shared__ float Bs[BK][BN + 4];

    const int tid = threadIdx.x;
    constexpr int TCOLS = BN / TN;
    const int tx = tid % TCOLS;
    const int ty = tid / TCOLS;
    const int m0 = blockIdx.y * BM;
    const int n0 = blockIdx.x * BN;

    float acc[TM][TN];
#pragma unroll
    for (int i = 0; i < TM; i++)
#pragma unroll
        for (int j = 0; j < TN; j++) acc[i][j] = 0.0f;

    for (int k0 = 0; k0 < K; k0 += BK) {
        for (int i = tid; i < BM * BK / 4; i += NT) {
            int r = i / (BK / 4);
            int c = (i % (BK / 4)) * 4;
            float4 v = *(const float4*)(A + (size_t)(m0 + r) * K + k0 + c);
            As[c + 0][r] = v.x;
            As[c + 1][r] = v.y;
            As[c + 2][r] = v.z;
            As[c + 3][r] = v.w;
        }
        for (int i = tid; i < BK * BN / 4; i += NT) {
            int r = i / (BN / 4);
            int c = (i % (BN / 4)) * 4;
            *(float4*)&Bs[r][c] = *(const float4*)(B + (size_t)(k0 + r) * N + n0 + c);
        }
        __syncthreads();
#pragma unroll
        for (int k = 0; k < BK; k++) {
            float a[TM], bb[TN];
#pragma unroll
            for (int i = 0; i < TM; i++) a[i] = As[k][ty * TM + i];
#pragma unroll
            for (int j = 0; j < TN; j++) bb[j] = Bs[k][tx * TN + j];
#pragma unroll
            for (int i = 0; i < TM; i++)
#pragma unroll
                for (int j = 0; j < TN; j++)
                    acc[i][j] = fmaf(a[i], bb[j], acc[i][j]);
        }
        __syncthreads();
    }

#pragma unroll
    for (int i = 0; i < TM; i++) {
        int m = m0 + ty * TM + i;
#pragma unroll
        for (int j = 0; j < TN; j++) {
            int n = n0 + tx * TN + j;
            float v = acc[i][j] + bias[n];
            if (RELU) v = fmaxf(v, 0.0f);
            C[(size_t)m * N + n] = v;
        }
    }
}

// ---------------------------------------------------------------------------
// 5) Final projection
// ---------------------------------------------------------------------------
__global__ void final_kernel(const float* __restrict__ mol,
                             const float* __restrict__ Wp,
                             const float* __restrict__ bp,
                             float* __restrict__ out) {
    int b = blockIdx.x;
    float s = 0.0f;
    for (int d = threadIdx.x; d < DIM; d += 128)
        s = fmaf(mol[(size_t)b * DIM + d], Wp[d], s);
    __shared__ float red[4];
#pragma unroll
    for (int o = 16; o; o >>= 1) s += __shfl_down_sync(0xFFFFFFFFu, s, o);
    if ((threadIdx.x & 31) == 0) red[threadIdx.x >> 5] = s;
    __syncthreads();
    if (threadIdx.x == 0)
        out[b] = red[0] + red[1] + red[2] + red[3] + bp[0];
}

// ---------------------------------------------------------------------------
// Launcher
// ---------------------------------------------------------------------------
extern "C" void kernel_launch(void* const* d_in, const int* in_sizes, int n_in,
                              void* d_out, int out_size) {
    const int*   fp    = (const int*)  d_in[0];
    const float* adj   = (const float*)d_in[1];
    const float* embed = (const float*)d_in[2];
    const float* Wf    = (const float*)d_in[3];
    const float* bf    = (const float*)d_in[4];
    const float* Wo    = (const float*)d_in[5];
    const float* bo    = (const float*)d_in[6];
    const float* Wp    = (const float*)d_in[7];
    const float* bp    = (const float*)d_in[8];
    float* out = (float*)d_out;

    float *H, *M0, *M1;
    __half *Vh, *Vl, *Wth, *Wtl;
    cudaGetSymbolAddress((void**)&H,   g_H);
    cudaGetSymbolAddress((void**)&Vh,  g_Vh);
    cudaGetSymbolAddress((void**)&Vl,  g_Vl);
    cudaGetSymbolAddress((void**)&Wth, g_Wth);
    cudaGetSymbolAddress((void**)&Wtl, g_Wtl);
    cudaGetSymbolAddress((void**)&M0,  g_mol);
    cudaGetSymbolAddress((void**)&M1,  g_mol2);

    cudaFuncSetAttribute(msg_norm_kernel<false>,
                         cudaFuncAttributeMaxDynamicSharedMemorySize, MSG_SMEM_BYTES);
    cudaFuncSetAttribute(msg_norm_kernel<true>,
                         cudaFuncAttributeMaxDynamicSharedMemorySize, MSG_SMEM_BYTES);
    cudaFuncSetAttribute(hgemm_split,
                         cudaFuncAttributeMaxDynamicSharedMemorySize, HG_SMEM);

    transpose_split_w<<<dim3(16, 16, LHID), dim3(32, 8)>>>(Wf);   // launch 0
    gather_embed<<<NROWS, 128>>>(fp, embed);                      // launch 1
    nop_kernel<<<1, 32>>>();                                      // launch 2 (ncu idx5 = hgemm)

    for (int l = 0; l < LHID; l++) {
        hgemm_split<<<dim3(DIM / 128, NROWS / 128), HG_THREADS, HG_SMEM>>>(
            Vh, Vl,
            Wth + (size_t)l * DIM * DIM, Wtl + (size_t)l * DIM * DIM,
            bf + (size_t)l * DIM, H);
        if (l + 1 < LHID)
            msg_norm_kernel<false><<<BATCH, 256, MSG_SMEM_BYTES>>>(adj);
        else
            msg_norm_kernel<true><<<BATCH, 256, MSG_SMEM_BYTES>>>(adj);
    }

    const float* src = M0;
    float* dst = M1;
    for (int i = 0; i < LOUT; i++) {
        sgemm_bias_kernel<32, 64, 16, 2, 4, true>
            <<<dim3(DIM / 64, BATCH / 32), 256>>>(
                src, Wo + (size_t)i * DIM * DIM, bo + (size_t)i * DIM,
                dst, BATCH, DIM, DIM);
        const float* t = src; src = dst; dst = (float*)t;
    }

    final_kernel<<<BATCH, 128>>>(src, Wp, bp, out);
}

// round 13
// speedup vs baseline: 2.6273x; 1.1328x over previous
#include <cuda_runtime.h>
#include <cuda_fp16.h>
#include <cstdint>
#include <cstddef>

// Problem constants
#define BATCH   512
#define NATOMS  32
#define DIM     512
#define NROWS   (BATCH * NATOMS)     // 16384
#define LHID    6
#define LOUT    6

// ---------------------------------------------------------------------------
// Scratch (static device globals; allocation-free per harness rules)
// ---------------------------------------------------------------------------
__device__ float  g_H [(size_t)NROWS * DIM];                      // 32 MB H2 out
__device__ __align__(16) __half g_Vh[(size_t)NROWS * DIM];        // 16 MB act hi
__device__ __align__(16) __half g_Vl[(size_t)NROWS * DIM];        // 16 MB act lo
__device__ __align__(16) __half g_Wth[(size_t)LHID * DIM * DIM];  // 3 MB W hi (K-major)
__device__ __align__(16) __half g_Wtl[(size_t)LHID * DIM * DIM];  // 3 MB W lo (K-major)
__device__ float  g_mol [(size_t)BATCH * DIM];
__device__ float  g_mol2[(size_t)BATCH * DIM];

// ---------------------------------------------------------------------------
// PTX helpers
// ---------------------------------------------------------------------------
__device__ __forceinline__ uint32_t smem_to_u32(const void* p) {
    uint32_t a;
    asm("{ .reg .u64 t; cvta.to.shared.u64 t, %1; cvt.u32.u64 %0, t; }" : "=r"(a) : "l"(p));
    return a;
}
#define CP_ASYNC16(dst, src) \
    asm volatile("cp.async.cg.shared.global [%0], [%1], 16;" :: "r"(dst), "l"(src))
#define CP_COMMIT() asm volatile("cp.async.commit_group;" ::: "memory")
#define CP_WAIT0()  asm volatile("cp.async.wait_group 0;" ::: "memory")
#define LDSM4(R0, R1, R2, R3, addr) \
    asm volatile("ldmatrix.sync.aligned.m8n8.x4.shared.b16 {%0,%1,%2,%3}, [%4];" \
        : "=r"(R0), "=r"(R1), "=r"(R2), "=r"(R3) : "r"(addr))

__device__ __forceinline__ void mma16816(float* d, const uint32_t* a, const uint32_t* b) {
    asm volatile(
        "mma.sync.aligned.m16n8k16.row.col.f32.f16.f16.f32 "
        "{%0,%1,%2,%3}, {%4,%5,%6,%7}, {%8,%9}, {%0,%1,%2,%3};"
        : "+f"(d[0]), "+f"(d[1]), "+f"(d[2]), "+f"(d[3])
        : "r"(a[0]), "r"(a[1]), "r"(a[2]), "r"(a[3]), "r"(b[0]), "r"(b[1]));
}
__device__ __forceinline__ void mma16816_f16(uint32_t* d, const uint32_t* a, const uint32_t* b) {
    asm volatile(
        "mma.sync.aligned.m16n8k16.row.col.f16.f16.f16.f16 "
        "{%0,%1}, {%2,%3,%4,%5}, {%6,%7}, {%0,%1};"
        : "+r"(d[0]), "+r"(d[1])
        : "r"(a[0]), "r"(a[1]), "r"(a[2]), "r"(a[3]), "r"(b[0]), "r"(b[1]));
}

// ---------------------------------------------------------------------------
// 0) Weight transpose + fp16 hi/lo split: Wt*[l][n][k] = split(Wf[l][k][n])
// ---------------------------------------------------------------------------
__global__ void transpose_split_w(const float* __restrict__ Wf) {
    __shared__ float t[32][33];
    const int l  = blockIdx.z;
    const int k0 = blockIdx.y * 32, n0 = blockIdx.x * 32;
    const int tx = threadIdx.x, ty = threadIdx.y;     // 32 x 8
    const float* src = Wf + (size_t)l * DIM * DIM;
#pragma unroll
    for (int i = 0; i < 4; i++)
        t[ty + i * 8][tx] = src[(size_t)(k0 + ty + i * 8) * DIM + n0 + tx];
    __syncthreads();
#pragma unroll
    for (int i = 0; i < 4; i++) {
        float v = t[tx][ty + i * 8];                  // = Wf[k0+tx][n0+ty+i*8]
        size_t dst = (size_t)l * DIM * DIM + (size_t)(n0 + ty + i * 8) * DIM + k0 + tx;
        __half hi = __float2half_rn(v);
        g_Wth[dst] = hi;
        g_Wtl[dst] = __float2half_rn(v - __half2float(hi));
    }
}

// ---------------------------------------------------------------------------
// 1) Gather + split: Vh/Vl[row,:] = split(embed[fp[row],:])
// ---------------------------------------------------------------------------
__global__ void gather_embed(const int* __restrict__ fp,
                             const float* __restrict__ embed) {
    int row = blockIdx.x;                  // 16384 blocks, 128 threads
    int f = fp[row];
    float4 v = ((const float4*)(embed + (size_t)f * DIM))[threadIdx.x];
    size_t o = (size_t)row * DIM + threadIdx.x * 4;
    __half hx = __float2half_rn(v.x), hy = __float2half_rn(v.y);
    __half hz = __float2half_rn(v.z), hw = __float2half_rn(v.w);
    *(__half2*)(g_Vh + o)     = __halves2half2(hx, hy);
    *(__half2*)(g_Vh + o + 2) = __halves2half2(hz, hw);
    *(__half2*)(g_Vl + o)     = __halves2half2(__float2half_rn(v.x - __half2float(hx)),
                                               __float2half_rn(v.y - __half2float(hy)));
    *(__half2*)(g_Vl + o + 2) = __halves2half2(__float2half_rn(v.z - __half2float(hz)),
                                               __float2half_rn(v.w - __half2float(hw)));
}

// Tiny pacing kernel: shifts launch indices so ncu (-s 5) lands on hgemm_fused.
__global__ void nop_kernel() {}

// ---------------------------------------------------------------------------
// 2) fused GEMM + message passing:
//    h  = relu(V @ Wf + bf)           (3-term fp16 split, tensor cores)
//    H2 = h + A_blockdiag @ h         (fp32 FMA epilogue, per-molecule)
//    CTA tile 64x128 (2 molecules x 128 cols), 8 warps of 32x32, KC=64.
//    256 threads, 2 CTAs/SM for epilogue/mainloop cross-CTA overlap.
// ---------------------------------------------------------------------------
#define KC2     64
#define NCH     (DIM / KC2)            // 8 chunks
#define A_OPB   (64  * KC2 * 2)        // 8192  bytes (A operand per stage)
#define B_OPB   (128 * KC2 * 2)        // 16384 bytes (B operand per stage)
#define STAGEB  (2 * A_OPB + 2 * B_OPB)    // 49152 bytes
#define HG_SMEM (2 * STAGEB)               // 98304 bytes
#define HG_THREADS 256

__device__ __forceinline__ void hg_issue(
    int c, int m0, int n0, uint32_t smem_u32, int tid,
    const __half* __restrict__ Ah, const __half* __restrict__ Al,
    const __half* __restrict__ Bh, const __half* __restrict__ Bl) {
    const int k0 = c * KC2;
    const uint32_t sbase = smem_u32 + (c & 1) * STAGEB;
    // A operands: 64 rows x 8 chunks = 512 chunks each
#pragma unroll
    for (int i = 0; i < 2; i++) {
        int idx = tid + i * HG_THREADS;       // 0..511
        int r = idx >> 3, ch = idx & 7;
        uint32_t doff = (uint32_t)(r * 128 + ((ch ^ (r & 7)) * 16));
        size_t go = (size_t)(m0 + r) * DIM + k0 + ch * 8;
        CP_ASYNC16(sbase + 0 * A_OPB + doff, Ah + go);
        CP_ASYNC16(sbase + 1 * A_OPB + doff, Al + go);
    }
    // B operands: 128 rows x 8 chunks = 1024 chunks each
#pragma unroll
    for (int i = 0; i < 4; i++) {
        int idx = tid + i * HG_THREADS;       // 0..1023
        int r = idx >> 3, ch = idx & 7;
        uint32_t doff = (uint32_t)(r * 128 + ((ch ^ (r & 7)) * 16));
        size_t go = (size_t)(n0 + r) * DIM + k0 + ch * 8;
        CP_ASYNC16(sbase + 2 * A_OPB + 0 * B_OPB + doff, Bh + go);
        CP_ASYNC16(sbase + 2 * A_OPB + 1 * B_OPB + doff, Bl + go);
    }
}

__global__ void __launch_bounds__(HG_THREADS, 2)
hgemm_fused(const __half* __restrict__ Ah, const __half* __restrict__ Al,
            const __half* __restrict__ Bh, const __half* __restrict__ Bl,
            const float* __restrict__ bias, const float* __restrict__ adj,
            float* __restrict__ C) {
    extern __shared__ __half hsm[];
    const uint32_t smem_u32 = smem_to_u32(hsm);
    const int tid = threadIdx.x;
    const int lane = tid & 31, wid = tid >> 5;       // 8 warps
    const int m0 = blockIdx.y * 64, n0 = blockIdx.x * 128;
    const int wm = (wid >> 2) * 32, wn = (wid & 3) * 32;   // 2x4 warp grid
    const int g = lane >> 2, tg = lane & 3;

    const int lrow = lane & 15, lsel = lane >> 4, lsw = lrow & 7;

    const uint32_t rA0 = (uint32_t)((wm + lrow) * 128);
    const uint32_t rA1 = (uint32_t)((wm + 16 + lrow) * 128);
    const uint32_t rB0 = (uint32_t)((wn + lrow) * 128);
    const uint32_t rB1 = (uint32_t)((wn + 16 + lrow) * 128);

    float acc[2][4][4];
    uint32_t accc[2][4][2];                   // fp16 correction accumulators
#pragma unroll
    for (int i = 0; i < 2; i++)
#pragma unroll
        for (int j = 0; j < 4; j++) {
#pragma unroll
            for (int r = 0; r < 4; r++) acc[i][j][r] = 0.0f;
            accc[i][j][0] = 0u; accc[i][j][1] = 0u;
        }

    hg_issue(0, m0, n0, smem_u32, tid, Ah, Al, Bh, Bl);
    CP_COMMIT();

    for (int c = 0; c < NCH; c++) {
        CP_WAIT0();
        __syncthreads();
        if (c + 1 < NCH) {
            hg_issue(c + 1, m0, n0, smem_u32, tid, Ah, Al, Bh, Bl);
            CP_COMMIT();
        }
        const uint32_t sb = smem_u32 + (c & 1) * STAGEB;
        const uint32_t aH = sb, aL = sb + A_OPB;
        const uint32_t bH = sb + 2 * A_OPB, bL = bH + B_OPB;

#pragma unroll
        for (int ks = 0; ks < KC2 / 16; ks++) {
            const uint32_t swz = (uint32_t)((((ks * 2) + lsel) ^ lsw) * 16);
            uint32_t a_hi[2][4], a_lo[2][4], b_hi[2][4], b_lo[2][4];

            LDSM4(a_hi[0][0], a_hi[0][1], a_hi[0][2], a_hi[0][3], aH + rA0 + swz);
            LDSM4(a_hi[1][0], a_hi[1][1], a_hi[1][2], a_hi[1][3], aH + rA1 + swz);
            LDSM4(b_hi[0][0], b_hi[0][1], b_hi[0][2], b_hi[0][3], bH + rB0 + swz);
            LDSM4(b_hi[1][0], b_hi[1][1], b_hi[1][2], b_hi[1][3], bH + rB1 + swz);
            // term 1: Ah * Bh (fp32 acc)
#pragma unroll
            for (int mf = 0; mf < 2; mf++)
#pragma unroll
                for (int nf = 0; nf < 4; nf++) {
                    int p = nf >> 1, o = nf & 1;
                    uint32_t bf[2] = { b_hi[p][o], b_hi[p][o + 2] };
                    mma16816(acc[mf][nf], a_hi[mf], bf);
                }
            // term 3: Ah * Bl (fp16 acc)
            LDSM4(b_lo[0][0], b_lo[0][1], b_lo[0][2], b_lo[0][3], bL + rB0 + swz);
            LDSM4(b_lo[1][0], b_lo[1][1], b_lo[1][2], b_lo[1][3], bL + rB1 + swz);
#pragma unroll
            for (int mf = 0; mf < 2; mf++)
#pragma unroll
                for (int nf = 0; nf < 4; nf++) {
                    int p = nf >> 1, o = nf & 1;
                    uint32_t bf[2] = { b_lo[p][o], b_lo[p][o + 2] };
                    mma16816_f16(accc[mf][nf], a_hi[mf], bf);
                }
            // term 2: Al * Bh (fp16 acc)
            LDSM4(a_lo[0][0], a_lo[0][1], a_lo[0][2], a_lo[0][3], aL + rA0 + swz);
            LDSM4(a_lo[1][0], a_lo[1][1], a_lo[1][2], a_lo[1][3], aL + rA1 + swz);
#pragma unroll
            for (int mf = 0; mf < 2; mf++)
#pragma unroll
                for (int nf = 0; nf < 4; nf++) {
                    int p = nf >> 1, o = nf & 1;
                    uint32_t bf[2] = { b_hi[p][o], b_hi[p][o + 2] };
                    mma16816_f16(accc[mf][nf], a_lo[mf], bf);
                }
        }
        __syncthreads();
    }

    // ---- Fused epilogue: h = relu(acc + corr + bias); H2 = h + A.h ----
    // smem reuse: hs [64][130] fp32 (33280 B), adjs 2x32x32 fp32 (8192 B)
    float* hs   = (float*)hsm;
    float* adjs = hs + 64 * 130;

    // store relu'd h tile
#pragma unroll
    for (int mf = 0; mf < 2; mf++) {
        int row = wm + mf * 16 + g;
#pragma unroll
        for (int nf = 0; nf < 4; nf++) {
            int col = wn + nf * 8 + tg * 2;
            float b0 = bias[n0 + col], b1 = bias[n0 + col + 1];
            __half2 c01 = *(__half2*)&accc[mf][nf][0];
            __half2 c23 = *(__half2*)&accc[mf][nf][1];
            float2 o0, o1;
            o0.x = fmaxf(acc[mf][nf][0] + __low2float(c01)  + b0, 0.0f);
            o0.y = fmaxf(acc[mf][nf][1] + __high2float(c01) + b1, 0.0f);
            o1.x = fmaxf(acc[mf][nf][2] + __low2float(c23)  + b0, 0.0f);
            o1.y = fmaxf(acc[mf][nf][3] + __high2float(c23) + b1, 0.0f);
            *(float2*)&hs[row * 130 + col] = o0;
            *(float2*)&hs[(row + 8) * 130 + col] = o1;
        }
    }
    // load adjacency blocks for the CTA's 2 molecules
    {
        const float* asrc = adj + (size_t)m0 * 32;     // (m0/32)*1024
#pragma unroll
        for (int i = 0; i < 8; i++)
            adjs[tid + i * 256] = asrc[tid + i * 256];
    }
    __syncthreads();

    // message passing: out[n][c] = h[n][c] + sum_m A[n][m]*h[m][c]
    {
        const int mol = wid >> 2;                      // 0..1
        const int c   = (wid & 3) * 32 + lane;         // 0..127
        float hm[32];
#pragma unroll
        for (int m = 0; m < 32; m++)
            hm[m] = hs[(mol * 32 + m) * 130 + c];
        const float* ar = adjs + mol * 1024;
        float* dst = C + (size_t)(m0 + mol * 32) * DIM + n0 + c;
#pragma unroll
        for (int n = 0; n < 32; n++) {
            float s = hm[n];
#pragma unroll
            for (int mq = 0; mq < 8; mq++) {
                float4 a4 = *(const float4*)&ar[n * 32 + mq * 4];
                s = fmaf(a4.x, hm[mq * 4 + 0], s);
                s = fmaf(a4.y, hm[mq * 4 + 1], s);
                s = fmaf(a4.z, hm[mq * 4 + 2], s);
                s = fmaf(a4.w, hm[mq * 4 + 3], s);
            }
            dst[(size_t)n * DIM] = s;
        }
    }
}

// ---------------------------------------------------------------------------
// 3) norm_split: v = H2/max(||H2||_row, eps) -> Vh, Vl   (warp per row)
// ---------------------------------------------------------------------------
__global__ void norm_split_kernel() {
    const int row  = blockIdx.x * 8 + (threadIdx.x >> 5);
    const int lane = threadIdx.x & 31;
    const float4* src = (const float4*)(g_H + (size_t)row * DIM);
    float4 v[4];
    float ss = 0.0f;
#pragma unroll
    for (int i = 0; i < 4; i++) {
        v[i] = src[lane + i * 32];
        ss = fmaf(v[i].x, v[i].x, ss);
        ss = fmaf(v[i].y, v[i].y, ss);
        ss = fmaf(v[i].z, v[i].z, ss);
        ss = fmaf(v[i].w, v[i].w, ss);
    }
#pragma unroll
    for (int o = 16; o; o >>= 1) ss += __shfl_xor_sync(0xFFFFFFFFu, ss, o);
    const float inv = 1.0f / fmaxf(sqrtf(ss), 1e-12f);

    __half* dh = g_Vh + (size_t)row * DIM;
    __half* dl = g_Vl + (size_t)row * DIM;
#pragma unroll
    for (int i = 0; i < 4; i++) {
        float x0 = v[i].x * inv, x1 = v[i].y * inv;
        float x2 = v[i].z * inv, x3 = v[i].w * inv;
        __half h0 = __float2half_rn(x0), h1 = __float2half_rn(x1);
        __half h2 = __float2half_rn(x2), h3 = __float2half_rn(x3);
        __half2 hi01 = __halves2half2(h0, h1), hi23 = __halves2half2(h2, h3);
        __half2 lo01 = __halves2half2(__float2half_rn(x0 - __half2float(h0)),
                                      __float2half_rn(x1 - __half2float(h1)));
        __half2 lo23 = __halves2half2(__float2half_rn(x2 - __half2float(h2)),
                                      __float2half_rn(x3 - __half2float(h3)));
        int off = (lane + i * 32) * 4;
        *(__half2*)(dh + off)     = hi01;
        *(__half2*)(dh + off + 2) = hi23;
        *(__half2*)(dl + off)     = lo01;
        *(__half2*)(dl + off + 2) = lo23;
    }
}

// ---------------------------------------------------------------------------
// 4) final_pool: per molecule: invn per row, mol = mean_n(H2[n]*invn[n])
// ---------------------------------------------------------------------------
#define POOL_SMEM ((NATOMS * DIM + NATOMS) * (int)sizeof(float))

__global__ void final_pool_kernel() {
    extern __shared__ float sm[];
    float* h    = sm;                       // [32][512]
    float* invn = sm + NATOMS * DIM;        // [32]
    const int b   = blockIdx.x;
    const int tid = threadIdx.x;            // 256 threads

    {
        const float4* src = (const float4*)(g_H + (size_t)b * NATOMS * DIM);
        float4* dst = (float4*)h;
#pragma unroll
        for (int i = 0; i < (NATOMS * DIM / 4) / 256; i++)
            dst[tid + i * 256] = src[tid + i * 256];
    }
    __syncthreads();

    {
        const int w = tid >> 5, lane = tid & 31;
        for (int r = w * 4; r < w * 4 + 4; r++) {
            float ss = 0.0f;
#pragma unroll
            for (int i = 0; i < DIM / 32; i++) {
                float x = h[r * DIM + lane + i * 32];
                ss = fmaf(x, x, ss);
            }
#pragma unroll
            for (int o = 16; o; o >>= 1) ss += __shfl_xor_sync(0xFFFFFFFFu, ss, o);
            if (lane == 0) invn[r] = 1.0f / fmaxf(sqrtf(ss), 1e-12f);
        }
    }
    __syncthreads();

#pragma unroll
    for (int j = 0; j < 2; j++) {
        int dd = tid + j * 256;
        float s = 0.0f;
#pragma unroll
        for (int n = 0; n < NATOMS; n++)
            s = fmaf(h[n * DIM + dd], invn[n], s);
        g_mol[(size_t)b * DIM + dd] = s * (1.0f / NATOMS);
    }
}

// ---------------------------------------------------------------------------
// 5) Scalar SGEMM for the small MLP
// ---------------------------------------------------------------------------
template<int BM, int BN, int BK, int TM, int TN, bool RELU>
__global__ void sgemm_bias_kernel(const float* __restrict__ A,
                                  const float* __restrict__ B,
                                  const float* __restrict__ bias,
                                  float* __restrict__ C,
                                  int M, int N, int K) {
    constexpr int NT = (BM / TM) * (BN / TN);
    __shared__ float As[BK][BM + 4];
    __shared__ float Bs[BK][BN + 4];

    const int tid = threadIdx.x;
    constexpr int TCOLS = BN / TN;
    const int tx = tid % TCOLS;
    const int ty = tid / TCOLS;
    const int m0 = blockIdx.y * BM;
    const int n0 = blockIdx.x * BN;

    float acc[TM][TN];
#pragma unroll
    for (int i = 0; i < TM; i++)
#pragma unroll
        for (int j = 0; j < TN; j++) acc[i][j] = 0.0f;

    for (int k0 = 0; k0 < K; k0 += BK) {
        for (int i = tid; i < BM * BK / 4; i += NT) {
            int r = i / (BK / 4);
            int c = (i % (BK / 4)) * 4;
            float4 v = *(const float4*)(A + (size_t)(m0 + r) * K + k0 + c);
            As[c + 0][r] = v.x;
            As[c + 1][r] = v.y;
            As[c + 2][r] = v.z;
            As[c + 3][r] = v.w;
        }
        for (int i = tid; i < BK * BN / 4; i += NT) {
            int r = i / (BN / 4);
            int c = (i % (BN / 4)) * 4;
            *(float4*)&Bs[r][c] = *(const float4*)(B + (size_t)(k0 + r) * N + n0 + c);
        }
        __syncthreads();
#pragma unroll
        for (int k = 0; k < BK; k++) {
            float a[TM], bb[TN];
#pragma unroll
            for (int i = 0; i < TM; i++) a[i] = As[k][ty * TM + i];
#pragma unroll
            for (int j = 0; j < TN; j++) bb[j] = Bs[k][tx * TN + j];
#pragma unroll
            for (int i = 0; i < TM; i++)
#pragma unroll
                for (int j = 0; j < TN; j++)
                    acc[i][j] = fmaf(a[i], bb[j], acc[i][j]);
        }
        __syncthreads();
    }

#pragma unroll
    for (int i = 0; i < TM; i++) {
        int m = m0 + ty * TM + i;
#pragma unroll
        for (int j = 0; j < TN; j++) {
            int n = n0 + tx * TN + j;
            float v = acc[i][j] + bias[n];
            if (RELU) v = fmaxf(v, 0.0f);
            C[(size_t)m * N + n] = v;
        }
    }
}

// ---------------------------------------------------------------------------
// 6) Final projection
// ---------------------------------------------------------------------------
__global__ void final_kernel(const float* __restrict__ mol,
                             const float* __restrict__ Wp,
                             const float* __restrict__ bp,
                             float* __restrict__ out) {
    int b = blockIdx.x;
    float s = 0.0f;
    for (int d = threadIdx.x; d < DIM; d += 128)
        s = fmaf(mol[(size_t)b * DIM + d], Wp[d], s);
    __shared__ float red[4];
#pragma unroll
    for (int o = 16; o; o >>= 1) s += __shfl_down_sync(0xFFFFFFFFu, s, o);
    if ((threadIdx.x & 31) == 0) red[threadIdx.x >> 5] = s;
    __syncthreads();
    if (threadIdx.x == 0)
        out[b] = red[0] + red[1] + red[2] + red[3] + bp[0];
}

// ---------------------------------------------------------------------------
// Launcher
// ---------------------------------------------------------------------------
extern "C" void kernel_launch(void* const* d_in, const int* in_sizes, int n_in,
                              void* d_out, int out_size) {
    const int*   fp    = (const int*)  d_in[0];
    const float* adj   = (const float*)d_in[1];
    const float* embed = (const float*)d_in[2];
    const float* Wf    = (const float*)d_in[3];
    const float* bf    = (const float*)d_in[4];
    const float* Wo    = (const float*)d_in[5];
    const float* bo    = (const float*)d_in[6];
    const float* Wp    = (const float*)d_in[7];
    const float* bp    = (const float*)d_in[8];
    float* out = (float*)d_out;

    float *H, *M0, *M1;
    __half *Vh, *Vl, *Wth, *Wtl;
    cudaGetSymbolAddress((void**)&H,   g_H);
    cudaGetSymbolAddress((void**)&Vh,  g_Vh);
    cudaGetSymbolAddress((void**)&Vl,  g_Vl);
    cudaGetSymbolAddress((void**)&Wth, g_Wth);
    cudaGetSymbolAddress((void**)&Wtl, g_Wtl);
    cudaGetSymbolAddress((void**)&M0,  g_mol);
    cudaGetSymbolAddress((void**)&M1,  g_mol2);

    cudaFuncSetAttribute(hgemm_fused,
                         cudaFuncAttributeMaxDynamicSharedMemorySize, HG_SMEM);
    cudaFuncSetAttribute(final_pool_kernel,
                         cudaFuncAttributeMaxDynamicSharedMemorySize, POOL_SMEM);

    transpose_split_w<<<dim3(16, 16, LHID), dim3(32, 8)>>>(Wf);   // launch 0
    gather_embed<<<NROWS, 128>>>(fp, embed);                      // launch 1
    nop_kernel<<<1, 32>>>();                                      // launch 2 (ncu idx5 = hgemm)

    for (int l = 0; l < LHID; l++) {
        hgemm_fused<<<dim3(DIM / 128, NROWS / 64), HG_THREADS, HG_SMEM>>>(
            Vh, Vl,
            Wth + (size_t)l * DIM * DIM, Wtl + (size_t)l * DIM * DIM,
            bf + (size_t)l * DIM, adj, H);
        if (l + 1 < LHID)
            norm_split_kernel<<<NROWS / 8, 256>>>();
        else
            final_pool_kernel<<<BATCH, 256, POOL_SMEM>>>();
    }

    const float* src = M0;
    float* dst = M1;
    for (int i = 0; i < LOUT; i++) {
        sgemm_bias_kernel<32, 64, 16, 2, 4, true>
            <<<dim3(DIM / 64, BATCH / 32), 256>>>(
                src, Wo + (size_t)i * DIM * DIM, bo + (size_t)i * DIM,
                dst, BATCH, DIM, DIM);
        const float* t = src; src = dst; dst = (float*)t;
    }

    final_kernel<<<BATCH, 128>>>(src, Wp, bp, out);
}

// round 15
// speedup vs baseline: 3.1359x; 1.1936x over previous
#include <cuda_runtime.h>
#include <cuda_fp16.h>
#include <cstdint>
#include <cstddef>

// Problem constants
#define BATCH   512
#define NATOMS  32
#define DIM     512
#define NROWS   (BATCH * NATOMS)     // 16384
#define LHID    6
#define LOUT    6

// ---------------------------------------------------------------------------
// Scratch (static device globals; allocation-free per harness rules)
// ---------------------------------------------------------------------------
__device__ float  g_H [(size_t)NROWS * DIM];                       // 32 MB H2 out
__device__ __align__(16) __half g_Vh [(size_t)NROWS * DIM];        // 16 MB act hi
__device__ __align__(16) __half g_Vl [(size_t)NROWS * DIM];        // 16 MB act lo
__device__ __align__(16) __half g_Wth[(size_t)LHID * DIM * DIM];   // feature W hi
__device__ __align__(16) __half g_Wtl[(size_t)LHID * DIM * DIM];   // feature W lo
__device__ __align__(16) __half g_Woth[(size_t)LOUT * DIM * DIM];  // MLP W hi
__device__ __align__(16) __half g_Wotl[(size_t)LOUT * DIM * DIM];  // MLP W lo
__device__ __align__(16) __half g_Mh0[(size_t)BATCH * DIM];        // mol split ping
__device__ __align__(16) __half g_Ml0[(size_t)BATCH * DIM];
__device__ __align__(16) __half g_Mh1[(size_t)BATCH * DIM];        // mol split pong
__device__ __align__(16) __half g_Ml1[(size_t)BATCH * DIM];
__device__ float  g_molf[(size_t)BATCH * DIM];                     // fp32 MLP out

// ---------------------------------------------------------------------------
// PTX helpers
// ---------------------------------------------------------------------------
__device__ __forceinline__ uint32_t smem_to_u32(const void* p) {
    uint32_t a;
    asm("{ .reg .u64 t; cvta.to.shared.u64 t, %1; cvt.u32.u64 %0, t; }" : "=r"(a) : "l"(p));
    return a;
}
#define CP_ASYNC16(dst, src) \
    asm volatile("cp.async.cg.shared.global [%0], [%1], 16;" :: "r"(dst), "l"(src))
#define CP_COMMIT() asm volatile("cp.async.commit_group;" ::: "memory")
#define CP_WAIT0()  asm volatile("cp.async.wait_group 0;" ::: "memory")
#define LDSM4(R0, R1, R2, R3, addr) \
    asm volatile("ldmatrix.sync.aligned.m8n8.x4.shared.b16 {%0,%1,%2,%3}, [%4];" \
        : "=r"(R0), "=r"(R1), "=r"(R2), "=r"(R3) : "r"(addr))

__device__ __forceinline__ void mma16816(float* d, const uint32_t* a, const uint32_t* b) {
    asm volatile(
        "mma.sync.aligned.m16n8k16.row.col.f32.f16.f16.f32 "
        "{%0,%1,%2,%3}, {%4,%5,%6,%7}, {%8,%9}, {%0,%1,%2,%3};"
        : "+f"(d[0]), "+f"(d[1]), "+f"(d[2]), "+f"(d[3])
        : "r"(a[0]), "r"(a[1]), "r"(a[2]), "r"(a[3]), "r"(b[0]), "r"(b[1]));
}
__device__ __forceinline__ void mma16816_f16(uint32_t* d, const uint32_t* a, const uint32_t* b) {
    asm volatile(
        "mma.sync.aligned.m16n8k16.row.col.f16.f16.f16.f16 "
        "{%0,%1}, {%2,%3,%4,%5}, {%6,%7}, {%0,%1};"
        : "+r"(d[0]), "+r"(d[1])
        : "r"(a[0]), "r"(a[1]), "r"(a[2]), "r"(a[3]), "r"(b[0]), "r"(b[1]));
}

__device__ __forceinline__ void split_store(__half* dh, __half* dl, int off,
                                            float x0, float x1, float x2, float x3) {
    __half h0 = __float2half_rn(x0), h1 = __float2half_rn(x1);
    __half h2 = __float2half_rn(x2), h3 = __float2half_rn(x3);
    *(__half2*)(dh + off)     = __halves2half2(h0, h1);
    *(__half2*)(dh + off + 2) = __halves2half2(h2, h3);
    *(__half2*)(dl + off)     = __halves2half2(__float2half_rn(x0 - __half2float(h0)),
                                               __float2half_rn(x1 - __half2float(h1)));
    *(__half2*)(dl + off + 2) = __halves2half2(__float2half_rn(x2 - __half2float(h2)),
                                               __float2half_rn(x3 - __half2float(h3)));
}

// ---------------------------------------------------------------------------
// 0) Weight transpose + fp16 hi/lo split: dst[l][n][k] = split(src[l][k][n])
// ---------------------------------------------------------------------------
__global__ void transpose_split_w(const float* __restrict__ W,
                                  __half* __restrict__ dh,
                                  __half* __restrict__ dl) {
    __shared__ float t[32][33];
    const int l  = blockIdx.z;
    const int k0 = blockIdx.y * 32, n0 = blockIdx.x * 32;
    const int tx = threadIdx.x, ty = threadIdx.y;     // 32 x 8
    const float* src = W + (size_t)l * DIM * DIM;
#pragma unroll
    for (int i = 0; i < 4; i++)
        t[ty + i * 8][tx] = src[(size_t)(k0 + ty + i * 8) * DIM + n0 + tx];
    __syncthreads();
#pragma unroll
    for (int i = 0; i < 4; i++) {
        float v = t[tx][ty + i * 8];
        size_t dst = (size_t)l * DIM * DIM + (size_t)(n0 + ty + i * 8) * DIM + k0 + tx;
        __half hi = __float2half_rn(v);
        dh[dst] = hi;
        dl[dst] = __float2half_rn(v - __half2float(hi));
    }
}

// ---------------------------------------------------------------------------
// 1) Gather + split: Vh/Vl[row,:] = split(embed[fp[row],:])
// ---------------------------------------------------------------------------
__global__ void gather_embed(const int* __restrict__ fp,
                             const float* __restrict__ embed) {
    int row = blockIdx.x;
    int f = fp[row];
    float4 v = ((const float4*)(embed + (size_t)f * DIM))[threadIdx.x];
    split_store(g_Vh + (size_t)row * DIM, g_Vl + (size_t)row * DIM,
                threadIdx.x * 4, v.x, v.y, v.z, v.w);
}

// ---------------------------------------------------------------------------
// 2) fused GEMM + message passing (unchanged from R13):
//    h = relu(V @ Wf + bf); H2 = h + A.h   (CTA 64x128, 8 warps, KC=64)
// ---------------------------------------------------------------------------
#define KC2     64
#define NCH     (DIM / KC2)
#define A_OPB   (64  * KC2 * 2)
#define B_OPB   (128 * KC2 * 2)
#define STAGEB  (2 * A_OPB + 2 * B_OPB)
#define HG_SMEM (2 * STAGEB)
#define HG_THREADS 256

__device__ __forceinline__ void hg_issue(
    int c, int m0, int n0, uint32_t smem_u32, int tid,
    const __half* __restrict__ Ah, const __half* __restrict__ Al,
    const __half* __restrict__ Bh, const __half* __restrict__ Bl) {
    const int k0 = c * KC2;
    const uint32_t sbase = smem_u32 + (c & 1) * STAGEB;
#pragma unroll
    for (int i = 0; i < 2; i++) {
        int idx = tid + i * HG_THREADS;
        int r = idx >> 3, ch = idx & 7;
        uint32_t doff = (uint32_t)(r * 128 + ((ch ^ (r & 7)) * 16));
        size_t go = (size_t)(m0 + r) * DIM + k0 + ch * 8;
        CP_ASYNC16(sbase + 0 * A_OPB + doff, Ah + go);
        CP_ASYNC16(sbase + 1 * A_OPB + doff, Al + go);
    }
#pragma unroll
    for (int i = 0; i < 4; i++) {
        int idx = tid + i * HG_THREADS;
        int r = idx >> 3, ch = idx & 7;
        uint32_t doff = (uint32_t)(r * 128 + ((ch ^ (r & 7)) * 16));
        size_t go = (size_t)(n0 + r) * DIM + k0 + ch * 8;
        CP_ASYNC16(sbase + 2 * A_OPB + 0 * B_OPB + doff, Bh + go);
        CP_ASYNC16(sbase + 2 * A_OPB + 1 * B_OPB + doff, Bl + go);
    }
}

__global__ void __launch_bounds__(HG_THREADS, 2)
hgemm_fused(const __half* __restrict__ Ah, const __half* __restrict__ Al,
            const __half* __restrict__ Bh, const __half* __restrict__ Bl,
            const float* __restrict__ bias, const float* __restrict__ adj,
            float* __restrict__ C) {
    extern __shared__ __half hsm[];
    const uint32_t smem_u32 = smem_to_u32(hsm);
    const int tid = threadIdx.x;
    const int lane = tid & 31, wid = tid >> 5;
    const int m0 = blockIdx.y * 64, n0 = blockIdx.x * 128;
    const int wm = (wid >> 2) * 32, wn = (wid & 3) * 32;
    const int g = lane >> 2, tg = lane & 3;
    const int lrow = lane & 15, lsel = lane >> 4, lsw = lrow & 7;

    const uint32_t rA0 = (uint32_t)((wm + lrow) * 128);
    const uint32_t rA1 = (uint32_t)((wm + 16 + lrow) * 128);
    const uint32_t rB0 = (uint32_t)((wn + lrow) * 128);
    const uint32_t rB1 = (uint32_t)((wn + 16 + lrow) * 128);

    float acc[2][4][4];
    uint32_t accc[2][4][2];
#pragma unroll
    for (int i = 0; i < 2; i++)
#pragma unroll
        for (int j = 0; j < 4; j++) {
#pragma unroll
            for (int r = 0; r < 4; r++) acc[i][j][r] = 0.0f;
            accc[i][j][0] = 0u; accc[i][j][1] = 0u;
        }

    hg_issue(0, m0, n0, smem_u32, tid, Ah, Al, Bh, Bl);
    CP_COMMIT();

    for (int c = 0; c < NCH; c++) {
        CP_WAIT0();
        __syncthreads();
        if (c + 1 < NCH) {
            hg_issue(c + 1, m0, n0, smem_u32, tid, Ah, Al, Bh, Bl);
            CP_COMMIT();
        }
        const uint32_t sb = smem_u32 + (c & 1) * STAGEB;
        const uint32_t aH = sb, aL = sb + A_OPB;
        const uint32_t bH = sb + 2 * A_OPB, bL = bH + B_OPB;

#pragma unroll
        for (int ks = 0; ks < KC2 / 16; ks++) {
            const uint32_t swz = (uint32_t)((((ks * 2) + lsel) ^ lsw) * 16);
            uint32_t a_hi[2][4], a_lo[2][4], b_hi[2][4], b_lo[2][4];

            LDSM4(a_hi[0][0], a_hi[0][1], a_hi[0][2], a_hi[0][3], aH + rA0 + swz);
            LDSM4(a_hi[1][0], a_hi[1][1], a_hi[1][2], a_hi[1][3], aH + rA1 + swz);
            LDSM4(b_hi[0][0], b_hi[0][1], b_hi[0][2], b_hi[0][3], bH + rB0 + swz);
            LDSM4(b_hi[1][0], b_hi[1][1], b_hi[1][2], b_hi[1][3], bH + rB1 + swz);
#pragma unroll
            for (int mf = 0; mf < 2; mf++)
#pragma unroll
                for (int nf = 0; nf < 4; nf++) {
                    int p = nf >> 1, o = nf & 1;
                    uint32_t bf[2] = { b_hi[p][o], b_hi[p][o + 2] };
                    mma16816(acc[mf][nf], a_hi[mf], bf);
                }
            LDSM4(b_lo[0][0], b_lo[0][1], b_lo[0][2], b_lo[0][3], bL + rB0 + swz);
            LDSM4(b_lo[1][0], b_lo[1][1], b_lo[1][2], b_lo[1][3], bL + rB1 + swz);
#pragma unroll
            for (int mf = 0; mf < 2; mf++)
#pragma unroll
                for (int nf = 0; nf < 4; nf++) {
                    int p = nf >> 1, o = nf & 1;
                    uint32_t bf[2] = { b_lo[p][o], b_lo[p][o + 2] };
                    mma16816_f16(accc[mf][nf], a_hi[mf], bf);
                }
            LDSM4(a_lo[0][0], a_lo[0][1], a_lo[0][2], a_lo[0][3], aL + rA0 + swz);
            LDSM4(a_lo[1][0], a_lo[1][1], a_lo[1][2], a_lo[1][3], aL + rA1 + swz);
#pragma unroll
            for (int mf = 0; mf < 2; mf++)
#pragma unroll
                for (int nf = 0; nf < 4; nf++) {
                    int p = nf >> 1, o = nf & 1;
                    uint32_t bf[2] = { b_hi[p][o], b_hi[p][o + 2] };
                    mma16816_f16(accc[mf][nf], a_lo[mf], bf);
                }
        }
        __syncthreads();
    }

    // Fused epilogue: h = relu(acc + corr + bias); H2 = h + A.h
    float* hs   = (float*)hsm;            // [64][130]
    float* adjs = hs + 64 * 130;          // [2][32][32]

#pragma unroll
    for (int mf = 0; mf < 2; mf++) {
        int row = wm + mf * 16 + g;
#pragma unroll
        for (int nf = 0; nf < 4; nf++) {
            int col = wn + nf * 8 + tg * 2;
            float b0 = bias[n0 + col], b1 = bias[n0 + col + 1];
            __half2 c01 = *(__half2*)&accc[mf][nf][0];
            __half2 c23 = *(__half2*)&accc[mf][nf][1];
            float2 o0, o1;
            o0.x = fmaxf(acc[mf][nf][0] + __low2float(c01)  + b0, 0.0f);
            o0.y = fmaxf(acc[mf][nf][1] + __high2float(c01) + b1, 0.0f);
            o1.x = fmaxf(acc[mf][nf][2] + __low2float(c23)  + b0, 0.0f);
            o1.y = fmaxf(acc[mf][nf][3] + __high2float(c23) + b1, 0.0f);
            *(float2*)&hs[row * 130 + col] = o0;
            *(float2*)&hs[(row + 8) * 130 + col] = o1;
        }
    }
    {
        const float* asrc = adj + (size_t)m0 * 32;
#pragma unroll
        for (int i = 0; i < 8; i++)
            adjs[tid + i * 256] = asrc[tid + i * 256];
    }
    __syncthreads();

    {
        const int mol = wid >> 2;
        const int c   = (wid & 3) * 32 + lane;
        float hm[32];
#pragma unroll
        for (int m = 0; m < 32; m++)
            hm[m] = hs[(mol * 32 + m) * 130 + c];
        const float* ar = adjs + mol * 1024;
        float* dst = C + (size_t)(m0 + mol * 32) * DIM + n0 + c;
#pragma unroll
        for (int n = 0; n < 32; n++) {
            float s = hm[n];
#pragma unroll
            for (int mq = 0; mq < 8; mq++) {
                float4 a4 = *(const float4*)&ar[n * 32 + mq * 4];
                s = fmaf(a4.x, hm[mq * 4 + 0], s);
                s = fmaf(a4.y, hm[mq * 4 + 1], s);
                s = fmaf(a4.z, hm[mq * 4 + 2], s);
                s = fmaf(a4.w, hm[mq * 4 + 3], s);
            }
            dst[(size_t)n * DIM] = s;
        }
    }
}

// ---------------------------------------------------------------------------
// 3) norm_split: v = H2/max(||H2||_row, eps) -> Vh, Vl   (warp per row)
// ---------------------------------------------------------------------------
__global__ void norm_split_kernel() {
    const int row  = blockIdx.x * 8 + (threadIdx.x >> 5);
    const int lane = threadIdx.x & 31;
    const float4* src = (const float4*)(g_H + (size_t)row * DIM);
    float4 v[4];
    float ss = 0.0f;
#pragma unroll
    for (int i = 0; i < 4; i++) {
        v[i] = src[lane + i * 32];
        ss = fmaf(v[i].x, v[i].x, ss);
        ss = fmaf(v[i].y, v[i].y, ss);
        ss = fmaf(v[i].z, v[i].z, ss);
        ss = fmaf(v[i].w, v[i].w, ss);
    }
#pragma unroll
    for (int o = 16; o; o >>= 1) ss += __shfl_xor_sync(0xFFFFFFFFu, ss, o);
    const float inv = 1.0f / fmaxf(sqrtf(ss), 1e-12f);
    __half* dh = g_Vh + (size_t)row * DIM;
    __half* dl = g_Vl + (size_t)row * DIM;
#pragma unroll
    for (int i = 0; i < 4; i++)
        split_store(dh, dl, (lane + i * 32) * 4,
                    v[i].x * inv, v[i].y * inv, v[i].z * inv, v[i].w * inv);
}

// ---------------------------------------------------------------------------
// 4) final_pool: mol = mean_n(H2[n]*invn[n]) -> fp16 split (Mh0, Ml0)
// ---------------------------------------------------------------------------
#define POOL_SMEM ((NATOMS * DIM + NATOMS) * (int)sizeof(float))

__global__ void final_pool_kernel() {
    extern __shared__ float sm[];
    float* h    = sm;
    float* invn = sm + NATOMS * DIM;
    const int b   = blockIdx.x;
    const int tid = threadIdx.x;          // 256 threads

    {
        const float4* src = (const float4*)(g_H + (size_t)b * NATOMS * DIM);
        float4* dst = (float4*)h;
#pragma unroll
        for (int i = 0; i < (NATOMS * DIM / 4) / 256; i++)
            dst[tid + i * 256] = src[tid + i * 256];
    }
    __syncthreads();
    {
        const int w = tid >> 5, lane = tid & 31;
        for (int r = w * 4; r < w * 4 + 4; r++) {
            float ss = 0.0f;
#pragma unroll
            for (int i = 0; i < DIM / 32; i++) {
                float x = h[r * DIM + lane + i * 32];
                ss = fmaf(x, x, ss);
            }
#pragma unroll
            for (int o = 16; o; o >>= 1) ss += __shfl_xor_sync(0xFFFFFFFFu, ss, o);
            if (lane == 0) invn[r] = 1.0f / fmaxf(sqrtf(ss), 1e-12f);
        }
    }
    __syncthreads();

#pragma unroll
    for (int j = 0; j < 2; j++) {
        int dd = tid + j * 256;
        float s = 0.0f;
#pragma unroll
        for (int n = 0; n < NATOMS; n++)
            s = fmaf(h[n * DIM + dd], invn[n], s);
        s *= (1.0f / NATOMS);
        __half hi = __float2half_rn(s);
        g_Mh0[(size_t)b * DIM + dd] = hi;
        g_Ml0[(size_t)b * DIM + dd] = __float2half_rn(s - __half2float(hi));
    }
}

// ---------------------------------------------------------------------------
// 5) MLP tensor GEMM: out = relu(M @ Wo + bo), 3-term split.
//    CTA 32x128, 8 warps of 16x32, KC=64. Writes fp16 split + fp32.
// ---------------------------------------------------------------------------
#define ML_A_OPB (32 * KC2 * 2)        // 4096
#define ML_B_OPB (128 * KC2 * 2)       // 16384
#define ML_STAGEB (2 * ML_A_OPB + 2 * ML_B_OPB)   // 40960
#define ML_SMEM (2 * ML_STAGEB)                   // 81920

__device__ __forceinline__ void ml_issue(
    int c, int m0, int n0, uint32_t smem_u32, int tid,
    const __half* __restrict__ Ah, const __half* __restrict__ Al,
    const __half* __restrict__ Bh, const __half* __restrict__ Bl) {
    const int k0 = c * KC2;
    const uint32_t sbase = smem_u32 + (c & 1) * ML_STAGEB;
    {
        int idx = tid;                     // 0..255 : 32 rows x 8 chunks
        int r = idx >> 3, ch = idx & 7;
        uint32_t doff = (uint32_t)(r * 128 + ((ch ^ (r & 7)) * 16));
        size_t go = (size_t)(m0 + r) * DIM + k0 + ch * 8;
        CP_ASYNC16(sbase + 0 * ML_A_OPB + doff, Ah + go);
        CP_ASYNC16(sbase + 1 * ML_A_OPB + doff, Al + go);
    }
#pragma unroll
    for (int i = 0; i < 4; i++) {
        int idx = tid + i * 256;           // 0..1023 : 128 rows x 8 chunks
        int r = idx >> 3, ch = idx & 7;
        uint32_t doff = (uint32_t)(r * 128 + ((ch ^ (r & 7)) * 16));
        size_t go = (size_t)(n0 + r) * DIM + k0 + ch * 8;
        CP_ASYNC16(sbase + 2 * ML_A_OPB + 0 * ML_B_OPB + doff, Bh + go);
        CP_ASYNC16(sbase + 2 * ML_A_OPB + 1 * ML_B_OPB + doff, Bl + go);
    }
}

__global__ void __launch_bounds__(256, 2)
mlp_gemm(const __half* __restrict__ Ah, const __half* __restrict__ Al,
         const __half* __restrict__ Bh, const __half* __restrict__ Bl,
         const float* __restrict__ bias,
         __half* __restrict__ Oh, __half* __restrict__ Ol,
         float* __restrict__ Of) {
    extern __shared__ __half hsm[];
    const uint32_t smem_u32 = smem_to_u32(hsm);
    const int tid = threadIdx.x;
    const int lane = tid & 31, wid = tid >> 5;
    const int m0 = blockIdx.y * 32, n0 = blockIdx.x * 128;
    const int wm = (wid >> 2) * 16, wn = (wid & 3) * 32;   // 2x4 grid of 16x32
    const int g = lane >> 2, tg = lane & 3;
    const int lrow = lane & 15, lsel = lane >> 4, lsw = lrow & 7;

    const uint32_t rA0 = (uint32_t)((wm + lrow) * 128);
    const uint32_t rB0 = (uint32_t)((wn + lrow) * 128);
    const uint32_t rB1 = (uint32_t)((wn + 16 + lrow) * 128);

    float acc[4][4];
    uint32_t accc[4][2];
#pragma unroll
    for (int j = 0; j < 4; j++) {
#pragma unroll
        for (int r = 0; r < 4; r++) acc[j][r] = 0.0f;
        accc[j][0] = 0u; accc[j][1] = 0u;
    }

    ml_issue(0, m0, n0, smem_u32, tid, Ah, Al, Bh, Bl);
    CP_COMMIT();

    for (int c = 0; c < NCH; c++) {
        CP_WAIT0();
        __syncthreads();
        if (c + 1 < NCH) {
            ml_issue(c + 1, m0, n0, smem_u32, tid, Ah, Al, Bh, Bl);
            CP_COMMIT();
        }
        const uint32_t sb = smem_u32 + (c & 1) * ML_STAGEB;
        const uint32_t aH = sb, aL = sb + ML_A_OPB;
        const uint32_t bH = sb + 2 * ML_A_OPB, bL = bH + ML_B_OPB;

#pragma unroll
        for (int ks = 0; ks < KC2 / 16; ks++) {
            const uint32_t swz = (uint32_t)((((ks * 2) + lsel) ^ lsw) * 16);
            uint32_t a_hi[4], a_lo[4], b_hi[2][4], b_lo[2][4];

            LDSM4(a_hi[0], a_hi[1], a_hi[2], a_hi[3], aH + rA0 + swz);
            LDSM4(b_hi[0][0], b_hi[0][1], b_hi[0][2], b_hi[0][3], bH + rB0 + swz);
            LDSM4(b_hi[1][0], b_hi[1][1], b_hi[1][2], b_hi[1][3], bH + rB1 + swz);
#pragma unroll
            for (int nf = 0; nf < 4; nf++) {
                int p = nf >> 1, o = nf & 1;
                uint32_t bf[2] = { b_hi[p][o], b_hi[p][o + 2] };
                mma16816(acc[nf], a_hi, bf);
            }
            LDSM4(b_lo[0][0], b_lo[0][1], b_lo[0][2], b_lo[0][3], bL + rB0 + swz);
            LDSM4(b_lo[1][0], b_lo[1][1], b_lo[1][2], b_lo[1][3], bL + rB1 + swz);
#pragma unroll
            for (int nf = 0; nf < 4; nf++) {
                int p = nf >> 1, o = nf & 1;
                uint32_t bf[2] = { b_lo[p][o], b_lo[p][o + 2] };
                mma16816_f16(accc[nf], a_hi, bf);
            }
            LDSM4(a_lo[0], a_lo[1], a_lo[2], a_lo[3], aL + rA0 + swz);
#pragma unroll
            for (int nf = 0; nf < 4; nf++) {
                int p = nf >> 1, o = nf & 1;
                uint32_t bf[2] = { b_hi[p][o], b_hi[p][o + 2] };
                mma16816_f16(accc[nf], a_lo, bf);
            }
        }
        __syncthreads();
    }

    // Epilogue: relu(acc + corr + bias) -> fp32 Of and split (Oh, Ol)
#pragma unroll
    for (int nf = 0; nf < 4; nf++) {
        int col = n0 + wn + nf * 8 + tg * 2;
        float b0 = bias[col], b1 = bias[col + 1];
        __half2 c01 = *(__half2*)&accc[nf][0];
        __half2 c23 = *(__half2*)&accc[nf][1];
        int r0 = m0 + wm + g;
        float v0 = fmaxf(acc[nf][0] + __low2float(c01)  + b0, 0.0f);
        float v1 = fmaxf(acc[nf][1] + __high2float(c01) + b1, 0.0f);
        float v2 = fmaxf(acc[nf][2] + __low2float(c23)  + b0, 0.0f);
        float v3 = fmaxf(acc[nf][3] + __high2float(c23) + b1, 0.0f);
        float2 w0 = {v0, v1}, w1 = {v2, v3};
        *(float2*)(Of + (size_t)r0 * DIM + col) = w0;
        *(float2*)(Of + (size_t)(r0 + 8) * DIM + col) = w1;
        __half h0 = __float2half_rn(v0), h1 = __float2half_rn(v1);
        __half h2 = __float2half_rn(v2), h3 = __float2half_rn(v3);
        *(__half2*)(Oh + (size_t)r0 * DIM + col) = __halves2half2(h0, h1);
        *(__half2*)(Ol + (size_t)r0 * DIM + col) =
            __halves2half2(__float2half_rn(v0 - __half2float(h0)),
                           __float2half_rn(v1 - __half2float(h1)));
        *(__half2*)(Oh + (size_t)(r0 + 8) * DIM + col) = __halves2half2(h2, h3);
        *(__half2*)(Ol + (size_t)(r0 + 8) * DIM + col) =
            __halves2half2(__float2half_rn(v2 - __half2float(h2)),
                           __float2half_rn(v3 - __half2float(h3)));
    }
}

// ---------------------------------------------------------------------------
// 6) Final projection: out[b] = molf[b,:] . Wp + bp
// ---------------------------------------------------------------------------
__global__ void final_kernel(const float* __restrict__ Wp,
                             const float* __restrict__ bp,
                             float* __restrict__ out) {
    int b = blockIdx.x;
    float s = 0.0f;
    for (int d = threadIdx.x; d < DIM; d += 128)
        s = fmaf(g_molf[(size_t)b * DIM + d], Wp[d], s);
    __shared__ float red[4];
#pragma unroll
    for (int o = 16; o; o >>= 1) s += __shfl_down_sync(0xFFFFFFFFu, s, o);
    if ((threadIdx.x & 31) == 0) red[threadIdx.x >> 5] = s;
    __syncthreads();
    if (threadIdx.x == 0)
        out[b] = red[0] + red[1] + red[2] + red[3] + bp[0];
}

// ---------------------------------------------------------------------------
// Launcher
// ---------------------------------------------------------------------------
extern "C" void kernel_launch(void* const* d_in, const int* in_sizes, int n_in,
                              void* d_out, int out_size) {
    const int*   fp    = (const int*)  d_in[0];
    const float* adj   = (const float*)d_in[1];
    const float* embed = (const float*)d_in[2];
    const float* Wf    = (const float*)d_in[3];
    const float* bf    = (const float*)d_in[4];
    const float* Wo    = (const float*)d_in[5];
    const float* bo    = (const float*)d_in[6];
    const float* Wp    = (const float*)d_in[7];
    const float* bp    = (const float*)d_in[8];
    float* out = (float*)d_out;

    float *H, *Molf;
    __half *Vh, *Vl, *Wth, *Wtl, *Woth, *Wotl, *Mh0, *Ml0, *Mh1, *Ml1;
    cudaGetSymbolAddress((void**)&H,    g_H);
    cudaGetSymbolAddress((void**)&Vh,   g_Vh);
    cudaGetSymbolAddress((void**)&Vl,   g_Vl);
    cudaGetSymbolAddress((void**)&Wth,  g_Wth);
    cudaGetSymbolAddress((void**)&Wtl,  g_Wtl);
    cudaGetSymbolAddress((void**)&Woth, g_Woth);
    cudaGetSymbolAddress((void**)&Wotl, g_Wotl);
    cudaGetSymbolAddress((void**)&Mh0,  g_Mh0);
    cudaGetSymbolAddress((void**)&Ml0,  g_Ml0);
    cudaGetSymbolAddress((void**)&Mh1,  g_Mh1);
    cudaGetSymbolAddress((void**)&Ml1,  g_Ml1);
    cudaGetSymbolAddress((void**)&Molf, g_molf);

    cudaFuncSetAttribute(hgemm_fused,
                         cudaFuncAttributeMaxDynamicSharedMemorySize, HG_SMEM);
    cudaFuncSetAttribute(mlp_gemm,
                         cudaFuncAttributeMaxDynamicSharedMemorySize, ML_SMEM);
    cudaFuncSetAttribute(final_pool_kernel,
                         cudaFuncAttributeMaxDynamicSharedMemorySize, POOL_SMEM);

    transpose_split_w<<<dim3(16, 16, LHID), dim3(32, 8)>>>(Wf, Wth, Wtl);   // 0
    transpose_split_w<<<dim3(16, 16, LOUT), dim3(32, 8)>>>(Wo, Woth, Wotl); // 1
    gather_embed<<<NROWS, 128>>>(fp, embed);                                // 2

    for (int l = 0; l < LHID; l++) {
        hgemm_fused<<<dim3(DIM / 128, NROWS / 64), HG_THREADS, HG_SMEM>>>(
            Vh, Vl,
            Wth + (size_t)l * DIM * DIM, Wtl + (size_t)l * DIM * DIM,
            bf + (size_t)l * DIM, adj, H);                                  // 3 (l0), 5 (l1) <- ncu
        if (l + 1 < LHID)
            norm_split_kernel<<<NROWS / 8, 256>>>();
        else
            final_pool_kernel<<<BATCH, 256, POOL_SMEM>>>();
    }

    __half *sh = Mh0, *sl = Ml0, *dh = Mh1, *dl = Ml1;
    for (int i = 0; i < LOUT; i++) {
        mlp_gemm<<<dim3(DIM / 128, BATCH / 32), 256, ML_SMEM>>>(
            sh, sl,
            Woth + (size_t)i * DIM * DIM, Wotl + (size_t)i * DIM * DIM,
            bo + (size_t)i * DIM, dh, dl, Molf);
        __half* t;
        t = sh; sh = dh; dh = t;
        t = sl; sl = dl; dl = t;
    }

    final_kernel<<<BATCH, 128>>>(Wp, bp, out);
}